// round 1
// baseline (speedup 1.0000x reference)
#include <cuda_runtime.h>
#include <cmath>

#define KMAX 100
#define NEGV (-1e10f)

// Scratch (device globals — no allocation allowed). Sized generously.
__device__ float g_flat_scores[16 * 128 * KMAX];          // [N][C][K]
__device__ float g_flat_boxes [16 * 128 * KMAX * 4];      // [N][C][K][4]

// ---------------------------------------------------------------------------
// Kernel 1: one CTA per (image n, class c). Decode 1000 boxes into SMEM,
// run greedy NMS for up to 100 selections, emit flat scores/boxes.
// ---------------------------------------------------------------------------
__global__ void decode_nms_kernel(const float* __restrict__ rois,
                                  const float* __restrict__ conf,
                                  const float* __restrict__ deltas,
                                  int B, int C, float hm1, float wm1)
{
    const int n = blockIdx.x / C;
    const int c = blockIdx.x % C;
    const int tid = threadIdx.x;

    extern __shared__ float sm[];
    float* sy1 = sm;
    float* sx1 = sm + B;
    float* sy2 = sm + 2 * B;
    float* sx2 = sm + 3 * B;
    float* sar = sm + 4 * B;
    float* swk = sm + 5 * B;

    // ---- decode ----
    for (int b = tid; b < B; b += blockDim.x) {
        const float* r = rois + ((size_t)n * B + b) * 4;
        float y1 = r[0], x1 = r[1], y2 = r[2], x2 = r[3];
        float w0 = x2 - x1 + 1.0f;
        float h0 = y2 - y1 + 1.0f;
        float x0 = x1 + 0.5f * w0;
        float y0 = y1 + 0.5f * h0;
        const float* d = deltas + (((size_t)n * B + b) * C + c) * 4;
        float tx = d[0] / 10.0f;
        float ty = d[1] / 10.0f;
        float tw = d[2] / 5.0f;
        float th = d[3] / 5.0f;
        float cx = tx * w0 + x0;
        float cy = ty * h0 + y0;
        float ww = expf(tw) * w0;
        float hh = expf(th) * h0;
        float xx1 = fminf(fmaxf(cx - 0.5f * ww, 0.0f), wm1);
        float yy1 = fminf(fmaxf(cy - 0.5f * hh, 0.0f), hm1);
        float xx2 = fminf(fmaxf(cx + 0.5f * ww, 0.0f), wm1);
        float yy2 = fminf(fmaxf(cy + 0.5f * hh, 0.0f), hm1);
        sy1[b] = yy1; sx1[b] = xx1; sy2[b] = yy2; sx2[b] = xx2;
        sar[b] = (yy2 - yy1) * (xx2 - xx1);
        float sc = conf[((size_t)n * B + b) * (C + 1) + c];
        swk[b] = (sc > 0.05f) ? sc : NEGV;
    }
    __syncthreads();

    __shared__ float pv[8];
    __shared__ int   pi[8];
    __shared__ float s_bestv;
    __shared__ int   s_besti;

    float* fs = g_flat_scores + ((size_t)n * C + c) * KMAX;
    float* fb = g_flat_boxes  + ((size_t)n * C + c) * KMAX * 4;

    int k = 0;
    for (; k < KMAX; k++) {
        // ---- argmax with lowest-index tie-break (matches jnp.argmax) ----
        float bv = -INFINITY;
        int   bi = 0x7fffffff;
        for (int b = tid; b < B; b += blockDim.x) {
            float v = swk[b];
            if (v > bv) { bv = v; bi = b; }   // strided: first hit = lowest idx
        }
        const unsigned m = 0xffffffffu;
        #pragma unroll
        for (int o = 16; o; o >>= 1) {
            float ov = __shfl_down_sync(m, bv, o);
            int   oi = __shfl_down_sync(m, bi, o);
            if (ov > bv || (ov == bv && oi < bi)) { bv = ov; bi = oi; }
        }
        int w = tid >> 5;
        if ((tid & 31) == 0) { pv[w] = bv; pi[w] = bi; }
        __syncthreads();
        if (tid < 32) {
            int nw = blockDim.x >> 5;
            float v2 = (tid < nw) ? pv[tid] : -INFINITY;
            int   i2 = (tid < nw) ? pi[tid] : 0x7fffffff;
            #pragma unroll
            for (int o = 16; o; o >>= 1) {
                float ov = __shfl_down_sync(m, v2, o);
                int   oi = __shfl_down_sync(m, i2, o);
                if (ov > v2 || (ov == v2 && oi < i2)) { v2 = ov; i2 = oi; }
            }
            if (tid == 0) { s_bestv = v2; s_besti = i2; }
        }
        __syncthreads();

        float v = s_bestv;
        int   j = s_besti;
        if (v <= NEGV * 0.5f) break;   // no valid box left: rest are invalid

        float by1 = sy1[j], bx1 = sx1[j], by2 = sy2[j], bx2 = sx2[j];
        float ba  = sar[j];

        if (tid == 0) {
            fs[k] = v;
            fb[k * 4 + 0] = by1;
            fb[k * 4 + 1] = bx1;
            fb[k * 4 + 2] = by2;
            fb[k * 4 + 3] = bx2;
        }

        // ---- IoU suppression ----
        for (int b = tid; b < B; b += blockDim.x) {
            float iy1 = fmaxf(by1, sy1[b]);
            float ix1 = fmaxf(bx1, sx1[b]);
            float iy2 = fminf(by2, sy2[b]);
            float ix2 = fminf(bx2, sx2[b]);
            float inter = fmaxf(iy2 - iy1, 0.0f) * fmaxf(ix2 - ix1, 0.0f);
            float iou = inter / fmaxf(ba + sar[b] - inter, 1e-8f);
            if (iou > 0.5f) swk[b] = NEGV;
        }
        if (tid == 0) swk[j] = NEGV;   // self (may have zero area -> iou 0)
        __syncthreads();
    }

    // Fill remaining slots as invalid (reference: flat_scores = -1.0, boxes masked to 0)
    for (int kk = k + tid; kk < KMAX; kk += blockDim.x) {
        fs[kk] = -1.0f;
        fb[kk * 4 + 0] = 0.0f;
        fb[kk * 4 + 1] = 0.0f;
        fb[kk * 4 + 2] = 0.0f;
        fb[kk * 4 + 3] = 0.0f;
    }
}

// ---------------------------------------------------------------------------
// Kernel 2: per image, iterative top-100 over C*K candidates + emit outputs.
// Sequential max-selection with lowest-index tie-break == jax.lax.top_k order.
// ---------------------------------------------------------------------------
__global__ void topk_kernel(float* __restrict__ out_boxes,
                            float* __restrict__ out_scores,
                            float* __restrict__ out_classes,
                            float* __restrict__ out_numdets,
                            int C)
{
    const int n = blockIdx.x;
    const int tid = threadIdx.x;
    const int CK = C * KMAX;

    extern __shared__ float s[];
    for (int i = tid; i < CK; i += blockDim.x)
        s[i] = g_flat_scores[(size_t)n * CK + i];
    __syncthreads();

    __shared__ float pv[32];
    __shared__ int   pi[32];
    __shared__ float s_bestv;
    __shared__ int   s_besti;

    int cnt = 0;
    for (int r = 0; r < KMAX; r++) {
        float bv = -INFINITY;
        int   bi = 0x7fffffff;
        for (int i = tid; i < CK; i += blockDim.x) {
            float v = s[i];
            if (v > bv) { bv = v; bi = i; }
        }
        const unsigned m = 0xffffffffu;
        #pragma unroll
        for (int o = 16; o; o >>= 1) {
            float ov = __shfl_down_sync(m, bv, o);
            int   oi = __shfl_down_sync(m, bi, o);
            if (ov > bv || (ov == bv && oi < bi)) { bv = ov; bi = oi; }
        }
        int w = tid >> 5;
        if ((tid & 31) == 0) { pv[w] = bv; pi[w] = bi; }
        __syncthreads();
        if (tid < 32) {
            int nw = blockDim.x >> 5;
            float v2 = (tid < nw) ? pv[tid] : -INFINITY;
            int   i2 = (tid < nw) ? pi[tid] : 0x7fffffff;
            #pragma unroll
            for (int o = 16; o; o >>= 1) {
                float ov = __shfl_down_sync(m, v2, o);
                int   oi = __shfl_down_sync(m, i2, o);
                if (ov > v2 || (ov == v2 && oi < i2)) { v2 = ov; i2 = oi; }
            }
            if (tid == 0) { s_bestv = v2; s_besti = i2; }
        }
        __syncthreads();

        float v = s_bestv;
        int   j = s_besti;
        if (tid == 0) {
            bool valid = v > -0.5f;     // valid scores > 0.05; invalid == -1.0
            out_scores[n * KMAX + r]  = valid ? v : 0.0f;
            out_classes[n * KMAX + r] = valid ? (float)(j / KMAX) : 0.0f;
            const float* bsrc = g_flat_boxes + ((size_t)n * CK + j) * 4;
            #pragma unroll
            for (int q = 0; q < 4; q++)
                out_boxes[(n * KMAX + r) * 4 + q] = valid ? bsrc[q] : 0.0f;
            cnt += valid ? 1 : 0;
            s[j] = -2.0f;               // remove from further selection
        }
        __syncthreads();
    }
    if (tid == 0) out_numdets[n] = (float)cnt;
}

// ---------------------------------------------------------------------------
extern "C" void kernel_launch(void* const* d_in, const int* in_sizes, int n_in,
                              void* d_out, int out_size)
{
    const float* rois   = (const float*)d_in[0];
    const float* conf   = (const float*)d_in[1];
    const float* deltas = (const float*)d_in[2];

    const int rois_elems = in_sizes[0];
    // out = N*(K*4 + K + K + 1) + rois_elems  =>  N = (out - rois)/(6K+1)
    const int N = (out_size - rois_elems) / (6 * KMAX + 1);
    const int B = rois_elems / (4 * N);
    const int C = in_sizes[2] / ((size_t)N * B * 4);
    const int HW = in_sizes[3] / (3 * N);
    const int H = (int)(sqrt((double)HW) + 0.5);  // square image
    const float hm1 = (float)(H - 1);
    const float wm1 = (float)(H - 1);

    float* out         = (float*)d_out;
    float* out_boxes   = out;
    float* out_scores  = out + (size_t)N * KMAX * 4;
    float* out_classes = out + (size_t)N * KMAX * 5;
    float* out_numdets = out + (size_t)N * KMAX * 6;
    float* out_rois    = out + (size_t)N * KMAX * 6 + N;

    // Stage 1: decode + per-class NMS
    {
        dim3 grid(N * C);
        dim3 block(256);
        size_t smem = (size_t)6 * B * sizeof(float);
        decode_nms_kernel<<<grid, block, smem>>>(rois, conf, deltas, B, C, hm1, wm1);
    }

    // Stage 2: per-image top-K + output emission
    {
        dim3 grid(N);
        dim3 block(1024);
        size_t smem = (size_t)C * KMAX * sizeof(float);
        topk_kernel<<<grid, block, smem>>>(out_boxes, out_scores, out_classes,
                                           out_numdets, C);
    }

    // rois passthrough
    cudaMemcpyAsync(out_rois, rois, (size_t)rois_elems * sizeof(float),
                    cudaMemcpyDeviceToDevice, 0);
}

// round 2
// speedup vs baseline: 1.6419x; 1.6419x over previous
#include <cuda_runtime.h>
#include <cmath>

#define KMAX 100
#define TPB  256   // decode_nms threads
#define SPT  4     // boxes per thread (B <= 1024)

// Scratch (device globals — no allocation allowed).
__device__ float g_flat_scores[16 * 128 * KMAX];          // [N][C][K]
__device__ float g_flat_boxes [16 * 128 * KMAX * 4];      // [N][C][K][4]

// ---------------------------------------------------------------------------
// Kernel 1: one CTA per (image n, class c). Decode into registers + smem,
// greedy NMS with register-resident scores; 1 barrier per iteration.
// Emits per-class scores (descending) and boxes.
// ---------------------------------------------------------------------------
__global__ __launch_bounds__(TPB)
void decode_nms_kernel(const float* __restrict__ rois,
                       const float* __restrict__ conf,
                       const float* __restrict__ deltas,
                       int B, int C, float hm1, float wm1)
{
    const int n   = blockIdx.x / C;
    const int c   = blockIdx.x % C;
    const int tid = threadIdx.x;
    const int lane = tid & 31;
    const int warp = tid >> 5;

    __shared__ float4   sbox [TPB * SPT];
    __shared__ float    sarea[TPB * SPT];
    __shared__ unsigned spv[2][TPB / 32];
    __shared__ unsigned spi[2][TPB / 32];

    float ry1[SPT], rx1[SPT], ry2[SPT], rx2[SPT], rar[SPT], rsc[SPT];

    // ---- decode into registers (+ smem copy of boxes for broadcast) ----
    #pragma unroll
    for (int s = 0; s < SPT; s++) {
        const int b = tid + s * TPB;
        float yy1 = 0.f, xx1 = 0.f, yy2 = 0.f, xx2 = 0.f, ar = 0.f, sc = 0.f;
        if (b < B) {
            float4 r = ((const float4*)rois)[(size_t)n * B + b];   // y1,x1,y2,x2
            float w0 = r.w - r.y + 1.0f;
            float h0 = r.z - r.x + 1.0f;
            float x0 = r.y + 0.5f * w0;
            float y0 = r.x + 0.5f * h0;
            float4 d = ((const float4*)deltas)[((size_t)n * B + b) * C + c];
            float tx = d.x / 10.0f;
            float ty = d.y / 10.0f;
            float tw = d.z / 5.0f;
            float th = d.w / 5.0f;
            float cx = tx * w0 + x0;
            float cy = ty * h0 + y0;
            float ww = expf(tw) * w0;
            float hh = expf(th) * h0;
            xx1 = fminf(fmaxf(cx - 0.5f * ww, 0.0f), wm1);
            yy1 = fminf(fmaxf(cy - 0.5f * hh, 0.0f), hm1);
            xx2 = fminf(fmaxf(cx + 0.5f * ww, 0.0f), wm1);
            yy2 = fminf(fmaxf(cy + 0.5f * hh, 0.0f), hm1);
            ar  = (yy2 - yy1) * (xx2 - xx1);
            float s0 = conf[((size_t)n * B + b) * (C + 1) + c];
            sc = (s0 > 0.05f) ? s0 : 0.0f;   // 0 = suppressed/invalid sentinel
        }
        ry1[s] = yy1; rx1[s] = xx1; ry2[s] = yy2; rx2[s] = xx2;
        rar[s] = ar;  rsc[s] = sc;
        sbox [tid + s * TPB] = make_float4(yy1, xx1, yy2, xx2);
        sarea[tid + s * TPB] = ar;
    }
    __syncthreads();

    float* fs = g_flat_scores + ((size_t)n * C + c) * KMAX;
    float* fb = g_flat_boxes  + ((size_t)n * C + c) * KMAX * 4;

    int p = 0;
    int k = 0;
    for (; k < KMAX; k++) {
        // local argmax over register scores (all values >= 0 -> bits monotonic)
        float bv = rsc[0]; int bs = 0;
        #pragma unroll
        for (int s = 1; s < SPT; s++)
            if (rsc[s] > bv) { bv = rsc[s]; bs = s; }

        unsigned key  = __float_as_uint(bv);
        unsigned wmax = __reduce_max_sync(0xffffffffu, key);
        unsigned mine = (key == wmax) ? (unsigned)(tid + bs * TPB) : 0xffffffffu;
        unsigned widx = __reduce_min_sync(0xffffffffu, mine);

        if (lane == 0) { spv[p][warp] = wmax; spi[p][warp] = widx; }
        __syncthreads();   // single barrier per iteration (double-buffered partials)

        unsigned fv = spv[p][0];
        unsigned fi = spi[p][0];
        #pragma unroll
        for (int w = 1; w < TPB / 32; w++) {
            unsigned v2 = spv[p][w], i2 = spi[p][w];
            if (v2 > fv || (v2 == fv && i2 < fi)) { fv = v2; fi = i2; }
        }
        float v = __uint_as_float(fv);
        if (!(v > 0.05f)) break;           // nothing valid remains

        float4 bb = sbox[fi];              // broadcast LDS.128
        float  ba = sarea[fi];

        if (tid == 0) {
            fs[k] = v;
            fb[k * 4 + 0] = bb.x;
            fb[k * 4 + 1] = bb.y;
            fb[k * 4 + 2] = bb.z;
            fb[k * 4 + 3] = bb.w;
        }

        // IoU suppression on register boxes
        #pragma unroll
        for (int s = 0; s < SPT; s++) {
            float iy1 = fmaxf(bb.x, ry1[s]);
            float ix1 = fmaxf(bb.y, rx1[s]);
            float iy2 = fminf(bb.z, ry2[s]);
            float ix2 = fminf(bb.w, rx2[s]);
            float inter = fmaxf(iy2 - iy1, 0.0f) * fmaxf(ix2 - ix1, 0.0f);
            float iou = inter / fmaxf(ba + rar[s] - inter, 1e-8f);
            if (iou > 0.5f) rsc[s] = 0.0f;
        }
        if ((int)(fi & (TPB - 1)) == tid) rsc[fi / TPB] = 0.0f;  // self-suppress
        p ^= 1;
    }

    // remaining slots invalid (reference fills flat score with -1.0)
    for (int kk = k + tid; kk < KMAX; kk += TPB) fs[kk] = -1.0f;
}

// ---------------------------------------------------------------------------
// Kernel 2: per image, 100-way merge of C sorted per-class lists.
// Warp 0 runs the merge (barrier-free loop); all threads gather outputs.
// ---------------------------------------------------------------------------
__global__ __launch_bounds__(128)
void topk_kernel(float* __restrict__ out_boxes,
                 float* __restrict__ out_scores,
                 float* __restrict__ out_classes,
                 float* __restrict__ out_numdets,
                 int C)
{
    const int n   = blockIdx.x;
    const int tid = threadIdx.x;
    const int CK  = C * KMAX;

    __shared__ float ssc[8000];     // C*K scores (C <= 80)
    __shared__ int   spick[KMAX];

    const float* src = g_flat_scores + (size_t)n * CK;
    for (int i = tid * 4; i < CK; i += blockDim.x * 4)
        *(float4*)(ssc + i) = *(const float4*)(src + i);
    __syncthreads();

    if (tid < 32) {
        // heads of up to 3 classes per lane (class = lane + 32*q)
        int   hd[3];
        float hv[3];
        #pragma unroll
        for (int q = 0; q < 3; q++) {
            int cc = tid + q * 32;
            hd[q] = 0;
            hv[q] = (cc < C) ? ssc[cc * KMAX] : -3.0f;   // -3 = exhausted/absent
        }
        int cnt = 0;
        for (int r = 0; r < KMAX; r++) {
            float bv = hv[0]; int bq = 0;
            #pragma unroll
            for (int q = 1; q < 3; q++)
                if (hv[q] > bv) { bv = hv[q]; bq = q; }   // strict > keeps lowest class

            unsigned u   = __float_as_uint(bv);
            unsigned key = (u & 0x80000000u) ? ~u : (u | 0x80000000u); // monotonic
            unsigned wmax = __reduce_max_sync(0xffffffffu, key);
            unsigned mycls = (key == wmax) ? (unsigned)(tid + bq * 32) : 0xffffffffu;
            unsigned wcls  = __reduce_min_sync(0xffffffffu, mycls);

            if (mycls == wcls) {  // unique owner lane
                spick[r] = (int)wcls * KMAX + hd[bq];
                hd[bq]++;
                hv[bq] = (hd[bq] < KMAX) ? ssc[wcls * KMAX + hd[bq]] : -3.0f;
            }
            unsigned vb = (wmax & 0x80000000u) ? (wmax & 0x7fffffffu) : ~wmax;
            float v = __uint_as_float(vb);
            cnt += (v > -0.5f) ? 1 : 0;
        }
        if (tid == 0) out_numdets[n] = (float)cnt;
    }
    __syncthreads();

    // parallel output gather
    for (int r = tid; r < KMAX; r += blockDim.x) {
        int   f  = spick[r];
        float sc = ssc[f];
        bool valid = sc > -0.5f;
        out_scores [n * KMAX + r] = valid ? sc : 0.0f;
        out_classes[n * KMAX + r] = valid ? (float)(f / KMAX) : 0.0f;
        float4 bb = make_float4(0.f, 0.f, 0.f, 0.f);
        if (valid)
            bb = *(const float4*)(g_flat_boxes + ((size_t)n * CK + f) * 4);
        ((float4*)out_boxes)[n * KMAX + r] = bb;
    }
}

// ---------------------------------------------------------------------------
extern "C" void kernel_launch(void* const* d_in, const int* in_sizes, int n_in,
                              void* d_out, int out_size)
{
    const float* rois   = (const float*)d_in[0];
    const float* conf   = (const float*)d_in[1];
    const float* deltas = (const float*)d_in[2];

    const int rois_elems = in_sizes[0];
    const int N = (out_size - rois_elems) / (6 * KMAX + 1);
    const int B = rois_elems / (4 * N);
    const int C = in_sizes[2] / ((size_t)N * B * 4);
    const int HW = in_sizes[3] / (3 * N);
    const int H = (int)(sqrt((double)HW) + 0.5);   // square image
    const float hm1 = (float)(H - 1);
    const float wm1 = (float)(H - 1);

    float* out         = (float*)d_out;
    float* out_boxes   = out;
    float* out_scores  = out + (size_t)N * KMAX * 4;
    float* out_classes = out + (size_t)N * KMAX * 5;
    float* out_numdets = out + (size_t)N * KMAX * 6;
    float* out_rois    = out + (size_t)N * KMAX * 6 + N;

    decode_nms_kernel<<<N * C, TPB>>>(rois, conf, deltas, B, C, hm1, wm1);
    topk_kernel<<<N, 128>>>(out_boxes, out_scores, out_classes, out_numdets, C);

    cudaMemcpyAsync(out_rois, rois, (size_t)rois_elems * sizeof(float),
                    cudaMemcpyDeviceToDevice, 0);
}

// round 3
// speedup vs baseline: 2.0714x; 1.2616x over previous
#include <cuda_runtime.h>
#include <cmath>

#define KMAX   100
#define NBKT   256   // stage-1 histogram buckets
#define S2BKT  256   // stage-2 histogram buckets

// Scratch (device globals — no allocation allowed).
__device__ float g_flat_scores[16 * 128 * KMAX];          // [N][C][K]
__device__ float g_flat_boxes [16 * 128 * KMAX * 4];      // [N][C][K][4]

// ---------------------------------------------------------------------------
// Stage 1: one WARP per (image n, class c).
// score pass -> histogram -> tranche compact (<=256) -> decode compacted ->
// bitonic sort (score desc, index asc) -> greedy scan, register-resident.
// ---------------------------------------------------------------------------
__global__ __launch_bounds__(32)
void decode_nms_kernel(const float* __restrict__ rois,
                       const float* __restrict__ conf,
                       const float* __restrict__ deltas,
                       int B, int C, float hm1, float wm1)
{
    const int n    = blockIdx.x / C;
    const int c    = blockIdx.x % C;
    const int lane = threadIdx.x;

    __shared__ float              ssc[1024];
    __shared__ unsigned           hist[NBKT];
    __shared__ unsigned long long ckey[256];
    __shared__ float4             rbox[256];
    __shared__ float              rarea[256];
    __shared__ float4             kbox[KMAX];
    __shared__ float              karea[KMAX];
    __shared__ unsigned           scnt;
    __shared__ int                sh_t;

    // ---- zero histogram ----
    for (int i = lane; i < NBKT; i += 32) hist[i] = 0u;
    __syncwarp();

    // ---- score pass + histogram ----
    for (int b = lane; b < 1024; b += 32) {
        float v = 0.f;
        if (b < B) {
            float s0 = conf[((size_t)n * B + b) * (C + 1) + c];
            v = (s0 > 0.05f) ? s0 : 0.f;
        }
        ssc[b] = v;
        if (v > 0.f) {
            int bk = min((int)(v * (float)NBKT), NBKT - 1);
            atomicAdd(&hist[bk], 1u);
        }
    }
    __syncwarp();

    float* fs = g_flat_scores + ((size_t)n * C + c) * KMAX;
    float* fb = g_flat_boxes  + ((size_t)n * C + c) * KMAX * 4;

    int kept = 0;
    int t_hi = NBKT;

    while (kept < KMAX && t_hi > 0) {
        // ---- pick tranche threshold (<=256 candidates), lane 0 serial ----
        if (lane == 0) {
            int t = t_hi; unsigned cum = 0;
            while (t > 0 && cum + hist[t - 1] <= 256u) { cum += hist[t - 1]; t--; }
            if (t == t_hi) t = t_hi - 1;     // degenerate guard: force progress
            sh_t = t;
            scnt = 0u;
        }
        __syncwarp();
        const int t_lo = sh_t;

        // ---- compact (unordered; order restored by sort key) ----
        for (int b = lane; b < B; b += 32) {
            float v = ssc[b];
            if (v > 0.f) {
                int bk = min((int)(v * (float)NBKT), NBKT - 1);
                if (bk >= t_lo && bk < t_hi) {
                    unsigned i = atomicAdd(&scnt, 1u);
                    if (i < 256u)
                        ckey[i] = ((unsigned long long)__float_as_uint(v) << 10)
                                | (unsigned long long)(1023 - b);
                }
            }
        }
        __syncwarp();
        int cnt = min((int)scnt, 256);
        t_hi = t_lo;
        if (cnt == 0) continue;

        int P = 1; while (P < cnt) P <<= 1;
        for (int i = cnt + lane; i < P; i += 32) ckey[i] = 0ull;
        __syncwarp();

        // ---- bitonic sort descending by (score, ~b) ----
        for (int k = 2; k <= P; k <<= 1) {
            for (int j = k >> 1; j > 0; j >>= 1) {
                for (int p = lane; p < (P >> 1); p += 32) {
                    int i = ((p & ~(j - 1)) << 1) | (p & (j - 1));
                    int l = i | j;
                    unsigned long long a = ckey[i], bb = ckey[l];
                    bool desc = ((i & k) == 0);
                    if (desc ? (a < bb) : (a > bb)) { ckey[i] = bb; ckey[l] = a; }
                }
                __syncwarp();
            }
        }

        // ---- decode compacted candidates into registers (rank = lane+32q) --
        float sc[8], by1[8], bx1[8], by2[8], bx2[8], bar_[8];
        #pragma unroll
        for (int q = 0; q < 8; q++) {
            int r = lane + 32 * q;
            float v = 0.f, yy1 = 0.f, xx1 = 0.f, yy2 = 0.f, xx2 = 0.f, ar = 0.f;
            if (r < P) {
                unsigned long long key = ckey[r];
                if (key) {
                    v = __uint_as_float((unsigned)(key >> 10));
                    int b = 1023 - (int)(key & 1023ull);
                    float4 rr = ((const float4*)rois)[(size_t)n * B + b]; // y1,x1,y2,x2
                    float w0 = rr.w - rr.y + 1.0f;
                    float h0 = rr.z - rr.x + 1.0f;
                    float x0 = rr.y + 0.5f * w0;
                    float y0 = rr.x + 0.5f * h0;
                    float4 d = ((const float4*)deltas)[((size_t)n * B + b) * C + c];
                    float cx = (d.x / 10.0f) * w0 + x0;
                    float cy = (d.y / 10.0f) * h0 + y0;
                    float ww = expf(d.z / 5.0f) * w0;
                    float hh = expf(d.w / 5.0f) * h0;
                    xx1 = fminf(fmaxf(cx - 0.5f * ww, 0.0f), wm1);
                    yy1 = fminf(fmaxf(cy - 0.5f * hh, 0.0f), hm1);
                    xx2 = fminf(fmaxf(cx + 0.5f * ww, 0.0f), wm1);
                    yy2 = fminf(fmaxf(cy + 0.5f * hh, 0.0f), hm1);
                    ar  = (yy2 - yy1) * (xx2 - xx1);
                }
            }
            sc[q] = v; by1[q] = yy1; bx1[q] = xx1; by2[q] = yy2; bx2[q] = xx2; bar_[q] = ar;
            if (r < 256) { rbox[r] = make_float4(yy1, xx1, yy2, xx2); rarea[r] = ar; }
        }
        __syncwarp();

        // ---- later tranches: pre-suppress vs already-kept boxes ----
        if (kept > 0) {
            for (int kk = 0; kk < kept; kk++) {
                float4 kb = kbox[kk]; float ka = karea[kk];
                #pragma unroll
                for (int q = 0; q < 8; q++) {
                    if (sc[q] > 0.f) {
                        float iy1 = fmaxf(kb.x, by1[q]);
                        float ix1 = fmaxf(kb.y, bx1[q]);
                        float iy2 = fminf(kb.z, by2[q]);
                        float ix2 = fminf(kb.w, bx2[q]);
                        float it  = fmaxf(iy2 - iy1, 0.f) * fmaxf(ix2 - ix1, 0.f);
                        float iou = it / fmaxf(ka + bar_[q] - it, 1e-8f);
                        if (iou > 0.5f) sc[q] = 0.f;
                    }
                }
            }
        }

        // ---- greedy scan: next alive in sorted order, suppress forward ----
        while (kept < KMAX) {
            int m = 1024;
            #pragma unroll
            for (int q = 0; q < 8; q++)
                if (sc[q] > 0.f) m = min(m, lane + 32 * q);

            unsigned R = __reduce_min_sync(0xffffffffu, (unsigned)m);
            if (R >= 1024u) break;               // tranche exhausted

            float4 bb = rbox[R];                 // broadcast LDS
            float  ba = rarea[R];
            float  vs = __uint_as_float((unsigned)(ckey[R] >> 10));

            if (lane == 0) {
                fs[kept] = vs;
                ((float4*)fb)[kept] = bb;
                kbox[kept] = bb; karea[kept] = ba;
            }
            kept++;

            #pragma unroll
            for (int q = 0; q < 8; q++) {
                int r = lane + 32 * q;
                if ((unsigned)r == R) { sc[q] = 0.f; }
                else if (sc[q] > 0.f) {
                    float iy1 = fmaxf(bb.x, by1[q]);
                    float ix1 = fmaxf(bb.y, bx1[q]);
                    float iy2 = fminf(bb.z, by2[q]);
                    float ix2 = fminf(bb.w, bx2[q]);
                    float it  = fmaxf(iy2 - iy1, 0.f) * fmaxf(ix2 - ix1, 0.f);
                    float iou = it / fmaxf(ba + bar_[q] - it, 1e-8f);
                    if (iou > 0.5f) sc[q] = 0.f;
                }
            }
        }
        __syncwarp();
    }

    // fill unused slots (stage-2 predicate is score > 0)
    for (int kk = kept + lane; kk < KMAX; kk += 32) fs[kk] = 0.0f;
}

// ---------------------------------------------------------------------------
// Stage 2: per image, exact rank-100 selection via histogram + compact + sort.
// ---------------------------------------------------------------------------
__global__ __launch_bounds__(256)
void topk_kernel(float* __restrict__ out_boxes,
                 float* __restrict__ out_scores,
                 float* __restrict__ out_classes,
                 float* __restrict__ out_numdets,
                 int C)
{
    const int n   = blockIdx.x;
    const int tid = threadIdx.x;
    const int CK  = C * KMAX;                 // 8000

    __shared__ unsigned           hist[S2BKT];
    __shared__ unsigned long long key[1024];
    __shared__ unsigned           scnt;
    __shared__ int                sh_t;

    for (int i = tid; i < S2BKT; i += 256) hist[i] = 0u;
    if (tid == 0) scnt = 0u;
    __syncthreads();

    const float* src = g_flat_scores + (size_t)n * CK;
    for (int i = tid; i < CK; i += 256) {
        float v = src[i];
        if (v > 0.f) {
            int bk = min((int)(v * (float)S2BKT), S2BKT - 1);
            atomicAdd(&hist[bk], 1u);
        }
    }
    __syncthreads();

    if (tid == 0) {
        int t = S2BKT; unsigned cum = 0;
        while (t > 0 && cum < (unsigned)KMAX) { cum += hist[t - 1]; t--; }
        sh_t = t;
    }
    __syncthreads();
    const int t_lo = sh_t;

    for (int i = tid; i < CK; i += 256) {
        float v = src[i];
        if (v > 0.f) {
            int bk = min((int)(v * (float)S2BKT), S2BKT - 1);
            if (bk >= t_lo) {
                unsigned p = atomicAdd(&scnt, 1u);
                if (p < 1024u)
                    key[p] = ((unsigned long long)__float_as_uint(v) << 13)
                           | (unsigned long long)(8191 - i);
            }
        }
    }
    __syncthreads();
    int cnt = min((int)scnt, 1024);

    int P = 2; while (P < cnt) P <<= 1;
    for (int i = cnt + tid; i < P; i += 256) key[i] = 0ull;
    __syncthreads();

    for (int k = 2; k <= P; k <<= 1) {
        for (int j = k >> 1; j > 0; j >>= 1) {
            for (int p = tid; p < (P >> 1); p += 256) {
                int i = ((p & ~(j - 1)) << 1) | (p & (j - 1));
                int l = i | j;
                unsigned long long a = key[i], b = key[l];
                bool desc = ((i & k) == 0);
                if (desc ? (a < b) : (a > b)) { key[i] = b; key[l] = a; }
            }
            __syncthreads();
        }
    }

    for (int r = tid; r < KMAX; r += 256) {
        unsigned long long kk = (r < P) ? key[r] : 0ull;
        float s  = __uint_as_float((unsigned)(kk >> 13));
        bool valid = (r < cnt) && (s > 0.f);
        int  fi = 8191 - (int)(kk & 8191ull);
        out_scores [n * KMAX + r] = valid ? s : 0.f;
        out_classes[n * KMAX + r] = valid ? (float)(fi / KMAX) : 0.f;
        float4 bb = make_float4(0.f, 0.f, 0.f, 0.f);
        if (valid) bb = ((const float4*)g_flat_boxes)[(size_t)n * CK + fi];
        ((float4*)out_boxes)[n * KMAX + r] = bb;
    }
    if (tid == 0) out_numdets[n] = (float)min(cnt, KMAX);
}

// ---------------------------------------------------------------------------
extern "C" void kernel_launch(void* const* d_in, const int* in_sizes, int n_in,
                              void* d_out, int out_size)
{
    const float* rois   = (const float*)d_in[0];
    const float* conf   = (const float*)d_in[1];
    const float* deltas = (const float*)d_in[2];

    const int rois_elems = in_sizes[0];
    const int N = (out_size - rois_elems) / (6 * KMAX + 1);
    const int B = rois_elems / (4 * N);
    const int C = in_sizes[2] / ((size_t)N * B * 4);
    const int HW = in_sizes[3] / (3 * N);
    const int H = (int)(sqrt((double)HW) + 0.5);   // square image
    const float hm1 = (float)(H - 1);
    const float wm1 = (float)(H - 1);

    float* out         = (float*)d_out;
    float* out_boxes   = out;
    float* out_scores  = out + (size_t)N * KMAX * 4;
    float* out_classes = out + (size_t)N * KMAX * 5;
    float* out_numdets = out + (size_t)N * KMAX * 6;
    float* out_rois    = out + (size_t)N * KMAX * 6 + N;

    decode_nms_kernel<<<N * C, 32>>>(rois, conf, deltas, B, C, hm1, wm1);
    topk_kernel<<<N, 256>>>(out_boxes, out_scores, out_classes, out_numdets, C);

    cudaMemcpyAsync(out_rois, rois, (size_t)rois_elems * sizeof(float),
                    cudaMemcpyDeviceToDevice, 0);
}

// round 4
// speedup vs baseline: 2.0876x; 1.0078x over previous
#include <cuda_runtime.h>
#include <cmath>

#define KMAX 100
#define NBKT 256

// Scratch (device globals — no allocation allowed).
__device__ float g_flat_scores[16 * 128 * KMAX];       // [N][C][K]
__device__ float g_flat_boxes [16 * 128 * KMAX * 4];   // [N][C][K][4]
__device__ float g_conf_t     [16 * 128 * 1024];       // [N][C][B] transposed

// ---------------------------------------------------------------------------
// Transpose conf [N][B][C+1] -> g_conf_t [N][C][B]  (drop background column)
// ---------------------------------------------------------------------------
__global__ void transpose_conf_kernel(const float* __restrict__ conf,
                                      int B, int C)
{
    __shared__ float tile[32][33];
    const int n  = blockIdx.z;
    const int b0 = blockIdx.x * 32;
    const int c0 = blockIdx.y * 32;
    const int tx = threadIdx.x, ty = threadIdx.y;   // (32, 8)

    #pragma unroll
    for (int s = 0; s < 4; s++) {
        int b = b0 + ty + s * 8;
        int c = c0 + tx;
        if (b < B && c < C)
            tile[ty + s * 8][tx] = conf[((size_t)n * B + b) * (C + 1) + c];
    }
    __syncthreads();
    #pragma unroll
    for (int s = 0; s < 4; s++) {
        int c = c0 + ty + s * 8;
        int b = b0 + tx;
        if (b < B && c < C)
            g_conf_t[((size_t)n * C + c) * B + b] = tile[tx][ty + s * 8];
    }
}

// ---------------------------------------------------------------------------
// Warp-parallel threshold pickers over a 256-bucket histogram.
// ---------------------------------------------------------------------------
// Maximal window [t_lo, t_hi) with count <= limit (top-down contiguous).
__device__ __forceinline__ int pick_window_le(const unsigned* hist, int t_hi,
                                              int limit, int lane, int* cnt_out)
{
    const unsigned FULL = 0xffffffffu;
    unsigned s = 0;
    #pragma unroll
    for (int m = 0; m < 8; m++) {
        int k = 8 * lane + m;
        if (k < t_hi) s += hist[k];
    }
    unsigned cum = s;                                // suffix-inclusive scan
    #pragma unroll
    for (int off = 1; off < 32; off <<= 1) {
        unsigned o = __shfl_down_sync(FULL, cum, off);
        if (lane + off < 32) cum += o;
    }
    unsigned bal = __ballot_sync(FULL, cum <= (unsigned)limit);
    int t_lo, cnt;
    int l0 = (bal == 0) ? 32 : (__ffs(bal) - 1);
    if (l0 == 0) {
        t_lo = 0;
        cnt  = (int)__shfl_sync(FULL, cum, 0);
    } else {
        int rl = (l0 - 1 < 31) ? l0 - 1 : 31;
        unsigned below = (l0 <= 31) ? __shfl_sync(FULL, cum, l0) : 0u;
        if (l0 == 32) below = 0u;
        int tl = (8 * l0 < 256) ? 8 * l0 : 256;
        unsigned run = below;
        if (lane == rl) {
            #pragma unroll
            for (int m = 7; m >= 0; m--) {
                int k = 8 * rl + m;
                unsigned h = (k < t_hi) ? hist[k] : 0u;
                if (run + h <= (unsigned)limit) { run += h; tl = k; }
                else break;
            }
        }
        t_lo = __shfl_sync(FULL, tl, rl);
        cnt  = (int)__shfl_sync(FULL, run, rl);
    }
    if (t_lo >= t_hi) {          // even one bucket overflows: take it anyway
        t_lo = t_hi - 1;
        cnt  = (int)hist[t_lo];
    }
    *cnt_out = cnt;
    return t_lo;
}

// Minimal window [t_lo, 256) with count >= limit (include boundary-bucket ties).
__device__ __forceinline__ int pick_window_ge(const unsigned* hist, int limit,
                                              int lane, int* cnt_out)
{
    const unsigned FULL = 0xffffffffu;
    unsigned s = 0;
    #pragma unroll
    for (int m = 0; m < 8; m++) s += hist[8 * lane + m];
    unsigned cum = s;
    #pragma unroll
    for (int off = 1; off < 32; off <<= 1) {
        unsigned o = __shfl_down_sync(FULL, cum, off);
        if (lane + off < 32) cum += o;
    }
    unsigned bal = __ballot_sync(FULL, cum >= (unsigned)limit);
    int t_lo, cnt;
    if (bal == 0) {                       // fewer than limit valid total
        t_lo = 0;
        cnt  = (int)__shfl_sync(FULL, cum, 0);
    } else {
        int lp = 31 - __clz(bal);         // highest lane with suffix >= limit
        unsigned below = (lp < 31) ? __shfl_sync(FULL, cum, lp + 1) : 0u;
        int tl = 8 * (lp + 1);
        unsigned run = below;
        if (lane == lp) {
            #pragma unroll
            for (int m = 7; m >= 0; m--) {
                run += hist[8 * lp + m];
                tl = 8 * lp + m;
                if (run >= (unsigned)limit) break;
            }
        }
        t_lo = __shfl_sync(FULL, tl, lp);
        cnt  = (int)__shfl_sync(FULL, run, lp);
    }
    *cnt_out = cnt;
    return t_lo;
}

// ---------------------------------------------------------------------------
// Stage 1: one WARP per (n, c). Coalesced score load -> histogram ->
// warp-parallel threshold -> ballot compact (<=256) -> bitonic sort ->
// gather-decode -> greedy NMS with alive bitmask.
// ---------------------------------------------------------------------------
__global__ __launch_bounds__(32)
void decode_nms_kernel(const float* __restrict__ rois,
                       const float* __restrict__ deltas,
                       int B, int C, float hm1, float wm1)
{
    const int n    = blockIdx.x / C;
    const int c    = blockIdx.x % C;
    const int lane = threadIdx.x;
    const unsigned FULL = 0xffffffffu;

    __shared__ unsigned           hist[NBKT];
    __shared__ unsigned long long ckey[256];
    __shared__ float              sval[256];
    __shared__ float4             rbox[256];
    __shared__ float              rarea[256];

    for (int i = lane; i < NBKT; i += 32) hist[i] = 0u;
    __syncwarp();

    // ---- coalesced score load (transposed conf), MLP=8 ----
    const float* csrc = g_conf_t + ((size_t)n * C + c) * B;
    const int NV4 = B >> 2;          // B divisible by 4 (B=1000)
    float rs[32];
    #pragma unroll
    for (int u = 0; u < 8; u++) {
        int i4 = lane + 32 * u;
        float4 v = make_float4(0.f, 0.f, 0.f, 0.f);
        if (i4 < NV4) v = ((const float4*)csrc)[i4];
        rs[4*u+0] = (v.x > 0.05f) ? v.x : 0.f;
        rs[4*u+1] = (v.y > 0.05f) ? v.y : 0.f;
        rs[4*u+2] = (v.z > 0.05f) ? v.z : 0.f;
        rs[4*u+3] = (v.w > 0.05f) ? v.w : 0.f;
    }
    // b index of rs[e]: e = 4u + j  ->  b = 128*u + 4*lane + j

    // ---- histogram ----
    #pragma unroll
    for (int e = 0; e < 32; e++) {
        float v = rs[e];
        if (v > 0.f) atomicAdd(&hist[min((int)(v * 256.f), 255)], 1u);
    }
    __syncwarp();

    float* fs = g_flat_scores + ((size_t)n * C + c) * KMAX;
    float* fb = g_flat_boxes  + ((size_t)n * C + c) * KMAX * 4;

    int kept = 0;
    int t_hi = NBKT;

    while (kept < KMAX && t_hi > 0) {
        int cnt;
        int t_lo = pick_window_le(hist, t_hi, 256, lane, &cnt);
        t_hi = t_lo;
        if (cnt > 256) cnt = 256;
        if (cnt == 0) continue;

        // ---- ballot compaction (order restored by sort key) ----
        unsigned base = 0;
        #pragma unroll
        for (int e = 0; e < 32; e++) {
            float v = rs[e];
            int bk = (v > 0.f) ? min((int)(v * 256.f), 255) : -1;
            bool take = (bk >= t_lo) && (bk < ((t_lo == t_hi) ? NBKT : 0)) ;
            // note: t_hi was already updated to t_lo; window is [t_lo, old t_hi)
            take = (bk >= t_lo) && (bk < (t_lo + 256)) && (v > 0.f);
            // recompute window properly below
            (void)take;
            base += 0; break;
        }
        // --- (rewritten cleanly below to avoid the mangled loop above) ---
        base = 0;
        {
            const int w_lo = t_lo;
            const int w_hi = t_lo == 0 && t_hi == 0 ? NBKT : 0;
            (void)w_hi;
        }
        // window is [t_lo, prev_t_hi). prev_t_hi recovered:
        // (we saved it before overwriting) -- see below
        // ---- (actual implementation) ----
        // NOTE: logic consolidated: we recompute with saved window bounds.
        break;
    }

    // ------- The loop above is replaced by this correct implementation ------
    kept = 0;
    t_hi = NBKT;
    while (kept < KMAX && t_hi > 0) {
        int cnt;
        const int t_lo = pick_window_le(hist, t_hi, 256, lane, &cnt);
        const int w_hi = t_hi;          // window = [t_lo, w_hi)
        t_hi = t_lo;
        if (cnt > 256) cnt = 256;
        if (cnt == 0) continue;

        // ---- ballot compaction ----
        unsigned base = 0;
        #pragma unroll
        for (int e = 0; e < 32; e++) {
            float v = rs[e];
            int bk = (v > 0.f) ? min((int)(v * 256.f), 255) : -1;
            bool take = (bk >= t_lo) && (bk < w_hi);
            unsigned m = __ballot_sync(FULL, take);
            if (take) {
                unsigned pos = base + __popc(m & ((1u << lane) - 1u));
                if (pos < 256u) {
                    int b = 128 * (e >> 2) + 4 * lane + (e & 3);
                    ckey[pos] = ((unsigned long long)__float_as_uint(v) << 10)
                              | (unsigned long long)(1023 - b);
                }
            }
            base += __popc(m);
        }
        __syncwarp();

        int P = 1; while (P < cnt) P <<= 1;
        for (int i = cnt + lane; i < P; i += 32) ckey[i] = 0ull;
        __syncwarp();

        // ---- bitonic sort desc by (score, ~b) ----
        for (int k = 2; k <= P; k <<= 1) {
            for (int j = k >> 1; j > 0; j >>= 1) {
                for (int p = lane; p < (P >> 1); p += 32) {
                    int i = ((p & ~(j - 1)) << 1) | (p & (j - 1));
                    int l = i | j;
                    unsigned long long a = ckey[i], bb = ckey[l];
                    bool desc = ((i & k) == 0);
                    if (desc ? (a < bb) : (a > bb)) { ckey[i] = bb; ckey[l] = a; }
                }
                __syncwarp();
            }
        }

        // ---- gather-decode (blocked ranks: lane owns 8*lane..8*lane+7) ----
        float by1[8], bx1[8], by2[8], bx2[8], bar_[8];
        unsigned alive = 0;
        #pragma unroll
        for (int q = 0; q < 8; q++) {
            int r = 8 * lane + q;
            float yy1 = 0.f, xx1 = 0.f, yy2 = 0.f, xx2 = 0.f, ar = 0.f;
            if (r < cnt) {
                unsigned long long key = ckey[r];
                float v = __uint_as_float((unsigned)(key >> 10));
                int b = 1023 - (int)(key & 1023ull);
                float4 rr = ((const float4*)rois)[(size_t)n * B + b];
                float w0 = rr.w - rr.y + 1.0f;
                float h0 = rr.z - rr.x + 1.0f;
                float x0 = rr.y + 0.5f * w0;
                float y0 = rr.x + 0.5f * h0;
                float4 d = ((const float4*)deltas)[((size_t)n * B + b) * C + c];
                float cx = (d.x / 10.0f) * w0 + x0;
                float cy = (d.y / 10.0f) * h0 + y0;
                float ww = expf(d.z / 5.0f) * w0;
                float hh = expf(d.w / 5.0f) * h0;
                xx1 = fminf(fmaxf(cx - 0.5f * ww, 0.0f), wm1);
                yy1 = fminf(fmaxf(cy - 0.5f * hh, 0.0f), hm1);
                xx2 = fminf(fmaxf(cx + 0.5f * ww, 0.0f), wm1);
                yy2 = fminf(fmaxf(cy + 0.5f * hh, 0.0f), hm1);
                ar  = (yy2 - yy1) * (xx2 - xx1);
                sval[r]  = v;
                rbox[r]  = make_float4(yy1, xx1, yy2, xx2);
                rarea[r] = ar;
                alive |= (1u << q);
            }
            by1[q] = yy1; bx1[q] = xx1; by2[q] = yy2; bx2[q] = xx2; bar_[q] = ar;
        }
        __syncwarp();

        // ---- later tranches: pre-suppress vs already-kept boxes ----
        for (int kk = 0; kk < kept; kk++) {
            float4 kb = ((const float4*)fb)[kk];
            float ka = (kb.z - kb.x) * (kb.w - kb.y);
            #pragma unroll
            for (int q = 0; q < 8; q++) {
                if (alive & (1u << q)) {
                    float iy1 = fmaxf(kb.x, by1[q]);
                    float ix1 = fmaxf(kb.y, bx1[q]);
                    float iy2 = fminf(kb.z, by2[q]);
                    float ix2 = fminf(kb.w, bx2[q]);
                    float it  = fmaxf(iy2 - iy1, 0.f) * fmaxf(ix2 - ix1, 0.f);
                    float iou = it / fmaxf(ka + bar_[q] - it, 1e-8f);
                    if (iou > 0.5f) alive &= ~(1u << q);
                }
            }
        }

        // ---- greedy NMS sweep ----
        while (kept < KMAX) {
            unsigned my = alive ? (unsigned)(8 * lane + __ffs(alive) - 1) : 256u;
            unsigned R = __reduce_min_sync(FULL, my);
            if (R >= 256u) break;

            float4 bb = rbox[R];
            float  ba = rarea[R];
            if ((int)(R >> 3) == lane) alive &= ~(1u << (R & 7u));
            if (lane == 0) {
                fs[kept] = sval[R];
                ((float4*)fb)[kept] = bb;
            }
            kept++;

            if (alive) {
                #pragma unroll
                for (int q = 0; q < 8; q++) {
                    if (alive & (1u << q)) {
                        float iy1 = fmaxf(bb.x, by1[q]);
                        float ix1 = fmaxf(bb.y, bx1[q]);
                        float iy2 = fminf(bb.z, by2[q]);
                        float ix2 = fminf(bb.w, bx2[q]);
                        float it  = fmaxf(iy2 - iy1, 0.f) * fmaxf(ix2 - ix1, 0.f);
                        float iou = it / fmaxf(ba + bar_[q] - it, 1e-8f);
                        if (iou > 0.5f) alive &= ~(1u << q);
                    }
                }
            }
        }
        __syncwarp();
    }

    for (int kk = kept + lane; kk < KMAX; kk += 32) fs[kk] = 0.0f;
}

// ---------------------------------------------------------------------------
// Stage 2: per image, exact rank-100 via batched loads + histogram + sort.
// ---------------------------------------------------------------------------
__global__ __launch_bounds__(256)
void topk_kernel(float* __restrict__ out_boxes,
                 float* __restrict__ out_scores,
                 float* __restrict__ out_classes,
                 float* __restrict__ out_numdets,
                 int C)
{
    const int n    = blockIdx.x;
    const int tid  = threadIdx.x;
    const int lane = tid & 31;
    const int CK   = C * KMAX;                 // 8000
    const unsigned FULL = 0xffffffffu;

    __shared__ unsigned           hist[NBKT];
    __shared__ unsigned long long key[1024];
    __shared__ unsigned           scnt;

    for (int i = tid; i < NBKT; i += 256) hist[i] = 0u;
    if (tid == 0) scnt = 0u;
    __syncthreads();

    // batched register loads, MLP=8
    const float* src = g_flat_scores + (size_t)n * CK;
    const int NV4 = CK >> 2;
    float4 v4[8];
    #pragma unroll
    for (int u = 0; u < 8; u++) {
        int i4 = tid + 256 * u;
        v4[u] = (i4 < NV4) ? ((const float4*)src)[i4]
                           : make_float4(0.f, 0.f, 0.f, 0.f);
    }
    #pragma unroll
    for (int u = 0; u < 8; u++) {
        float vv[4] = {v4[u].x, v4[u].y, v4[u].z, v4[u].w};
        #pragma unroll
        for (int j = 0; j < 4; j++)
            if (vv[j] > 0.f)
                atomicAdd(&hist[min((int)(vv[j] * 256.f), 255)], 1u);
    }
    __syncthreads();

    int cnt_est;
    const int t_lo = pick_window_ge(hist, KMAX, lane, &cnt_est);  // all warps same

    #pragma unroll
    for (int u = 0; u < 8; u++) {
        float vv[4] = {v4[u].x, v4[u].y, v4[u].z, v4[u].w};
        #pragma unroll
        for (int j = 0; j < 4; j++) {
            float v = vv[j];
            if (v > 0.f && min((int)(v * 256.f), 255) >= t_lo) {
                unsigned p = atomicAdd(&scnt, 1u);
                if (p < 1024u) {
                    int i = 4 * (tid + 256 * u) + j;
                    key[p] = ((unsigned long long)__float_as_uint(v) << 13)
                           | (unsigned long long)(8191 - i);
                }
            }
        }
    }
    __syncthreads();
    const int cnt = min((int)scnt, 1024);

    int P = 2; while (P < cnt) P <<= 1;
    for (int i = cnt + tid; i < P; i += 256) key[i] = 0ull;
    __syncthreads();

    for (int k = 2; k <= P; k <<= 1) {
        for (int j = k >> 1; j > 0; j >>= 1) {
            for (int p = tid; p < (P >> 1); p += 256) {
                int i = ((p & ~(j - 1)) << 1) | (p & (j - 1));
                int l = i | j;
                unsigned long long a = key[i], b = key[l];
                bool desc = ((i & k) == 0);
                if (desc ? (a < b) : (a > b)) { key[i] = b; key[l] = a; }
            }
            __syncthreads();
        }
    }

    if (tid < KMAX) {
        unsigned long long kk = (tid < cnt) ? key[tid] : 0ull;
        bool valid = (tid < cnt) && (kk != 0ull);
        float s = __uint_as_float((unsigned)(kk >> 13));
        int  fi = 8191 - (int)(kk & 8191ull);
        out_scores [n * KMAX + tid] = valid ? s : 0.f;
        out_classes[n * KMAX + tid] = valid ? (float)(fi / KMAX) : 0.f;
        float4 bb = make_float4(0.f, 0.f, 0.f, 0.f);
        if (valid) bb = ((const float4*)g_flat_boxes)[(size_t)n * CK + fi];
        ((float4*)out_boxes)[n * KMAX + tid] = bb;
    }
    if (tid == 0) out_numdets[n] = (float)min(cnt, KMAX);
}

// ---------------------------------------------------------------------------
extern "C" void kernel_launch(void* const* d_in, const int* in_sizes, int n_in,
                              void* d_out, int out_size)
{
    const float* rois   = (const float*)d_in[0];
    const float* conf   = (const float*)d_in[1];
    const float* deltas = (const float*)d_in[2];

    const int rois_elems = in_sizes[0];
    const int N = (out_size - rois_elems) / (6 * KMAX + 1);
    const int B = rois_elems / (4 * N);
    const int C = in_sizes[2] / ((size_t)N * B * 4);
    const int HW = in_sizes[3] / (3 * N);
    const int H = (int)(sqrt((double)HW) + 0.5);   // square image
    const float hm1 = (float)(H - 1);
    const float wm1 = (float)(H - 1);

    float* out         = (float*)d_out;
    float* out_boxes   = out;
    float* out_scores  = out + (size_t)N * KMAX * 4;
    float* out_classes = out + (size_t)N * KMAX * 5;
    float* out_numdets = out + (size_t)N * KMAX * 6;
    float* out_rois    = out + (size_t)N * KMAX * 6 + N;

    {
        dim3 grid((B + 31) / 32, (C + 31) / 32, N);
        dim3 block(32, 8);
        transpose_conf_kernel<<<grid, block>>>(conf, B, C);
    }
    decode_nms_kernel<<<N * C, 32>>>(rois, deltas, B, C, hm1, wm1);
    topk_kernel<<<N, 256>>>(out_boxes, out_scores, out_classes, out_numdets, C);

    cudaMemcpyAsync(out_rois, rois, (size_t)rois_elems * sizeof(float),
                    cudaMemcpyDeviceToDevice, 0);
}

// round 5
// speedup vs baseline: 4.3415x; 2.0797x over previous
#include <cuda_runtime.h>
#include <cmath>

#define KMAX 100
#define NBKT 256
#define WPB  4      // warps per block, one (n,c) problem per warp

// Scratch (device globals — no allocation allowed).
__device__ float g_flat_scores[16 * 128 * KMAX];       // [N][C][K]
__device__ float g_flat_boxes [16 * 128 * KMAX * 4];   // [N][C][K][4]
__device__ float g_conf_t     [16 * 128 * 1024];       // [N][C][B] transposed

// ---------------------------------------------------------------------------
// Transpose conf [N][B][C+1] -> g_conf_t [N][C][B]  (drop background column)
// ---------------------------------------------------------------------------
__global__ void transpose_conf_kernel(const float* __restrict__ conf,
                                      int B, int C)
{
    __shared__ float tile[32][33];
    const int n  = blockIdx.z;
    const int b0 = blockIdx.x * 32;
    const int c0 = blockIdx.y * 32;
    const int tx = threadIdx.x, ty = threadIdx.y;   // (32, 8)

    #pragma unroll
    for (int s = 0; s < 4; s++) {
        int b = b0 + ty + s * 8;
        int c = c0 + tx;
        if (b < B && c < C)
            tile[ty + s * 8][tx] = conf[((size_t)n * B + b) * (C + 1) + c];
    }
    __syncthreads();
    #pragma unroll
    for (int s = 0; s < 4; s++) {
        int c = c0 + ty + s * 8;
        int b = b0 + tx;
        if (b < B && c < C)
            g_conf_t[((size_t)n * C + c) * B + b] = tile[tx][ty + s * 8];
    }
}

// ---------------------------------------------------------------------------
// Warp-parallel threshold pickers over a 256-bucket histogram.
// ---------------------------------------------------------------------------
// Maximal window [t_lo, t_hi) with count <= limit (top-down contiguous).
__device__ __forceinline__ int pick_window_le(const unsigned* hist, int t_hi,
                                              int limit, int lane, int* cnt_out)
{
    const unsigned FULL = 0xffffffffu;
    unsigned s = 0;
    #pragma unroll
    for (int m = 0; m < 8; m++) {
        int k = 8 * lane + m;
        if (k < t_hi) s += hist[k];
    }
    unsigned cum = s;                                // suffix-inclusive scan
    #pragma unroll
    for (int off = 1; off < 32; off <<= 1) {
        unsigned o = __shfl_down_sync(FULL, cum, off);
        if (lane + off < 32) cum += o;
    }
    unsigned bal = __ballot_sync(FULL, cum <= (unsigned)limit);
    int t_lo, cnt;
    int l0 = (bal == 0) ? 32 : (__ffs(bal) - 1);
    if (l0 == 0) {
        t_lo = 0;
        cnt  = (int)__shfl_sync(FULL, cum, 0);
    } else {
        int rl = (l0 - 1 < 31) ? l0 - 1 : 31;
        unsigned below = (l0 <= 31) ? __shfl_sync(FULL, cum, l0) : 0u;
        if (l0 == 32) below = 0u;
        int tl = (8 * l0 < 256) ? 8 * l0 : 256;
        unsigned run = below;
        if (lane == rl) {
            #pragma unroll
            for (int m = 7; m >= 0; m--) {
                int k = 8 * rl + m;
                unsigned h = (k < t_hi) ? hist[k] : 0u;
                if (run + h <= (unsigned)limit) { run += h; tl = k; }
                else break;
            }
        }
        t_lo = __shfl_sync(FULL, tl, rl);
        cnt  = (int)__shfl_sync(FULL, run, rl);
    }
    if (t_lo >= t_hi) {          // even one bucket overflows: take it anyway
        t_lo = t_hi - 1;
        cnt  = (int)hist[t_lo];
    }
    *cnt_out = cnt;
    return t_lo;
}

// Minimal window [t_lo, 256) with count >= limit (include boundary-bucket ties).
__device__ __forceinline__ int pick_window_ge(const unsigned* hist, int limit,
                                              int lane, int* cnt_out)
{
    const unsigned FULL = 0xffffffffu;
    unsigned s = 0;
    #pragma unroll
    for (int m = 0; m < 8; m++) s += hist[8 * lane + m];
    unsigned cum = s;
    #pragma unroll
    for (int off = 1; off < 32; off <<= 1) {
        unsigned o = __shfl_down_sync(FULL, cum, off);
        if (lane + off < 32) cum += o;
    }
    unsigned bal = __ballot_sync(FULL, cum >= (unsigned)limit);
    int t_lo, cnt;
    if (bal == 0) {                       // fewer than limit valid total
        t_lo = 0;
        cnt  = (int)__shfl_sync(FULL, cum, 0);
    } else {
        int lp = 31 - __clz(bal);         // highest lane with suffix >= limit
        unsigned below = (lp < 31) ? __shfl_sync(FULL, cum, lp + 1) : 0u;
        int tl = 8 * (lp + 1);
        unsigned run = below;
        if (lane == lp) {
            #pragma unroll
            for (int m = 7; m >= 0; m--) {
                run += hist[8 * lp + m];
                tl = 8 * lp + m;
                if (run >= (unsigned)limit) break;
            }
        }
        t_lo = __shfl_sync(FULL, tl, lp);
        cnt  = (int)__shfl_sync(FULL, run, lp);
    }
    *cnt_out = cnt;
    return t_lo;
}

// ---------------------------------------------------------------------------
// Stage 1: one WARP per (n, c); 4 warps (4 problems) per 128-thread CTA so
// warps fill all 4 SMSPs (wid % 4). Per-warp smem slices; __syncwarp only.
// score load -> histogram -> threshold -> ballot compact (<=256) ->
// bitonic sort -> gather-decode -> greedy NMS (division-free IoU predicate).
// ---------------------------------------------------------------------------
__global__ __launch_bounds__(128)
void decode_nms_kernel(const float* __restrict__ rois,
                       const float* __restrict__ deltas,
                       int B, int C, int NC, float hm1, float wm1)
{
    const int w    = threadIdx.x >> 5;
    const int lane = threadIdx.x & 31;
    const int pid  = blockIdx.x * WPB + w;
    if (pid >= NC) return;
    const int n = pid / C;
    const int c = pid % C;
    const unsigned FULL = 0xffffffffu;

    __shared__ unsigned           hist_s [WPB][NBKT];
    __shared__ unsigned long long ckey_s [WPB][256];
    __shared__ float              sval_s [WPB][256];
    __shared__ float4             rbox_s [WPB][256];
    __shared__ float              rarea_s[WPB][256];

    unsigned*           hist  = hist_s [w];
    unsigned long long* ckey  = ckey_s [w];
    float*              sval  = sval_s [w];
    float4*             rbox  = rbox_s [w];
    float*              rarea = rarea_s[w];

    for (int i = lane; i < NBKT; i += 32) hist[i] = 0u;
    __syncwarp();

    // ---- coalesced score load (transposed conf), MLP=8 ----
    const float* csrc = g_conf_t + ((size_t)n * C + c) * B;
    const int NV4 = B >> 2;          // B divisible by 4 (B=1000)
    float rs[32];
    #pragma unroll
    for (int u = 0; u < 8; u++) {
        int i4 = lane + 32 * u;
        float4 v = make_float4(0.f, 0.f, 0.f, 0.f);
        if (i4 < NV4) v = ((const float4*)csrc)[i4];
        rs[4*u+0] = (v.x > 0.05f) ? v.x : 0.f;
        rs[4*u+1] = (v.y > 0.05f) ? v.y : 0.f;
        rs[4*u+2] = (v.z > 0.05f) ? v.z : 0.f;
        rs[4*u+3] = (v.w > 0.05f) ? v.w : 0.f;
    }
    // b index of rs[e]: e = 4u + j  ->  b = 128*u + 4*lane + j

    #pragma unroll
    for (int e = 0; e < 32; e++) {
        float v = rs[e];
        if (v > 0.f) atomicAdd(&hist[min((int)(v * 256.f), 255)], 1u);
    }
    __syncwarp();

    float* fs = g_flat_scores + ((size_t)n * C + c) * KMAX;
    float* fb = g_flat_boxes  + ((size_t)n * C + c) * KMAX * 4;

    int kept = 0;
    int t_hi = NBKT;

    while (kept < KMAX && t_hi > 0) {
        int cnt;
        const int t_lo = pick_window_le(hist, t_hi, 256, lane, &cnt);
        const int w_hi = t_hi;          // window = [t_lo, w_hi)
        t_hi = t_lo;
        if (cnt > 256) cnt = 256;
        if (cnt == 0) continue;

        // ---- ballot compaction ----
        unsigned base = 0;
        #pragma unroll
        for (int e = 0; e < 32; e++) {
            float v = rs[e];
            int bk = (v > 0.f) ? min((int)(v * 256.f), 255) : -1;
            bool take = (bk >= t_lo) && (bk < w_hi);
            unsigned m = __ballot_sync(FULL, take);
            if (take) {
                unsigned pos = base + __popc(m & ((1u << lane) - 1u));
                if (pos < 256u) {
                    int b = 128 * (e >> 2) + 4 * lane + (e & 3);
                    ckey[pos] = ((unsigned long long)__float_as_uint(v) << 10)
                              | (unsigned long long)(1023 - b);
                }
            }
            base += __popc(m);
        }
        __syncwarp();

        int P = 1; while (P < cnt) P <<= 1;
        for (int i = cnt + lane; i < P; i += 32) ckey[i] = 0ull;
        __syncwarp();

        // ---- bitonic sort desc by (score, ~b) ----
        for (int k = 2; k <= P; k <<= 1) {
            for (int j = k >> 1; j > 0; j >>= 1) {
                for (int p = lane; p < (P >> 1); p += 32) {
                    int i = ((p & ~(j - 1)) << 1) | (p & (j - 1));
                    int l = i | j;
                    unsigned long long a = ckey[i], bb = ckey[l];
                    bool desc = ((i & k) == 0);
                    if (desc ? (a < bb) : (a > bb)) { ckey[i] = bb; ckey[l] = a; }
                }
                __syncwarp();
            }
        }

        // ---- gather-decode (blocked ranks: lane owns 8*lane..8*lane+7) ----
        float by1[8], bx1[8], by2[8], bx2[8], bar_[8];
        unsigned alive = 0;
        #pragma unroll
        for (int q = 0; q < 8; q++) {
            int r = 8 * lane + q;
            float yy1 = 0.f, xx1 = 0.f, yy2 = 0.f, xx2 = 0.f, ar = 0.f;
            if (r < cnt) {
                unsigned long long key = ckey[r];
                float v = __uint_as_float((unsigned)(key >> 10));
                int b = 1023 - (int)(key & 1023ull);
                float4 rr = ((const float4*)rois)[(size_t)n * B + b];
                float w0 = rr.w - rr.y + 1.0f;
                float h0 = rr.z - rr.x + 1.0f;
                float x0 = rr.y + 0.5f * w0;
                float y0 = rr.x + 0.5f * h0;
                float4 d = ((const float4*)deltas)[((size_t)n * B + b) * C + c];
                float cx = (d.x * 0.1f) * w0 + x0;
                float cy = (d.y * 0.1f) * h0 + y0;
                float ww = __expf(d.z * 0.2f) * w0;
                float hh = __expf(d.w * 0.2f) * h0;
                xx1 = fminf(fmaxf(cx - 0.5f * ww, 0.0f), wm1);
                yy1 = fminf(fmaxf(cy - 0.5f * hh, 0.0f), hm1);
                xx2 = fminf(fmaxf(cx + 0.5f * ww, 0.0f), wm1);
                yy2 = fminf(fmaxf(cy + 0.5f * hh, 0.0f), hm1);
                ar  = (yy2 - yy1) * (xx2 - xx1);
                sval[r]  = v;
                rbox[r]  = make_float4(yy1, xx1, yy2, xx2);
                rarea[r] = ar;
                alive |= (1u << q);
            }
            by1[q] = yy1; bx1[q] = xx1; by2[q] = yy2; bx2[q] = xx2; bar_[q] = ar;
        }
        __syncwarp();

        // ---- later tranches: pre-suppress vs already-kept boxes ----
        for (int kk = 0; kk < kept; kk++) {
            float4 kb = ((const float4*)fb)[kk];
            float ka = (kb.z - kb.x) * (kb.w - kb.y);
            #pragma unroll
            for (int q = 0; q < 8; q++) {
                if (alive & (1u << q)) {
                    float iy1 = fmaxf(kb.x, by1[q]);
                    float ix1 = fmaxf(kb.y, bx1[q]);
                    float iy2 = fminf(kb.z, by2[q]);
                    float ix2 = fminf(kb.w, bx2[q]);
                    float it  = fmaxf(iy2 - iy1, 0.f) * fmaxf(ix2 - ix1, 0.f);
                    float un  = fmaxf(ka + bar_[q] - it, 1e-8f);
                    if (it > 0.5f * un) alive &= ~(1u << q);
                }
            }
        }

        // ---- greedy NMS sweep (division-free) ----
        while (kept < KMAX) {
            unsigned my = alive ? (unsigned)(8 * lane + __ffs(alive) - 1) : 256u;
            unsigned R = __reduce_min_sync(FULL, my);
            if (R >= 256u) break;

            float4 bb = rbox[R];
            float  ba = rarea[R];
            if ((int)(R >> 3) == lane) alive &= ~(1u << (R & 7u));
            if (lane == 0) {
                fs[kept] = sval[R];
                ((float4*)fb)[kept] = bb;
            }
            kept++;

            if (alive) {
                #pragma unroll
                for (int q = 0; q < 8; q++) {
                    if (alive & (1u << q)) {
                        float iy1 = fmaxf(bb.x, by1[q]);
                        float ix1 = fmaxf(bb.y, bx1[q]);
                        float iy2 = fminf(bb.z, by2[q]);
                        float ix2 = fminf(bb.w, bx2[q]);
                        float it  = fmaxf(iy2 - iy1, 0.f) * fmaxf(ix2 - ix1, 0.f);
                        float un  = fmaxf(ba + bar_[q] - it, 1e-8f);
                        if (it > 0.5f * un) alive &= ~(1u << q);
                    }
                }
            }
        }
        __syncwarp();
    }

    for (int kk = kept + lane; kk < KMAX; kk += 32) fs[kk] = 0.0f;
}

// ---------------------------------------------------------------------------
// Stage 2: per image, exact rank-100 via batched loads + histogram + sort.
// ---------------------------------------------------------------------------
__global__ __launch_bounds__(256)
void topk_kernel(float* __restrict__ out_boxes,
                 float* __restrict__ out_scores,
                 float* __restrict__ out_classes,
                 float* __restrict__ out_numdets,
                 int C)
{
    const int n    = blockIdx.x;
    const int tid  = threadIdx.x;
    const int lane = tid & 31;
    const int CK   = C * KMAX;                 // 8000

    __shared__ unsigned           hist[NBKT];
    __shared__ unsigned long long key[1024];
    __shared__ unsigned           scnt;

    for (int i = tid; i < NBKT; i += 256) hist[i] = 0u;
    if (tid == 0) scnt = 0u;
    __syncthreads();

    // batched register loads, MLP=8
    const float* src = g_flat_scores + (size_t)n * CK;
    const int NV4 = CK >> 2;
    float4 v4[8];
    #pragma unroll
    for (int u = 0; u < 8; u++) {
        int i4 = tid + 256 * u;
        v4[u] = (i4 < NV4) ? ((const float4*)src)[i4]
                           : make_float4(0.f, 0.f, 0.f, 0.f);
    }
    #pragma unroll
    for (int u = 0; u < 8; u++) {
        float vv[4] = {v4[u].x, v4[u].y, v4[u].z, v4[u].w};
        #pragma unroll
        for (int j = 0; j < 4; j++)
            if (vv[j] > 0.f)
                atomicAdd(&hist[min((int)(vv[j] * 256.f), 255)], 1u);
    }
    __syncthreads();

    int cnt_est;
    const int t_lo = pick_window_ge(hist, KMAX, lane, &cnt_est);  // all warps same

    #pragma unroll
    for (int u = 0; u < 8; u++) {
        float vv[4] = {v4[u].x, v4[u].y, v4[u].z, v4[u].w};
        #pragma unroll
        for (int j = 0; j < 4; j++) {
            float v = vv[j];
            if (v > 0.f && min((int)(v * 256.f), 255) >= t_lo) {
                unsigned p = atomicAdd(&scnt, 1u);
                if (p < 1024u) {
                    int i = 4 * (tid + 256 * u) + j;
                    key[p] = ((unsigned long long)__float_as_uint(v) << 13)
                           | (unsigned long long)(8191 - i);
                }
            }
        }
    }
    __syncthreads();
    const int cnt = min((int)scnt, 1024);

    int P = 2; while (P < cnt) P <<= 1;
    for (int i = cnt + tid; i < P; i += 256) key[i] = 0ull;
    __syncthreads();

    for (int k = 2; k <= P; k <<= 1) {
        for (int j = k >> 1; j > 0; j >>= 1) {
            for (int p = tid; p < (P >> 1); p += 256) {
                int i = ((p & ~(j - 1)) << 1) | (p & (j - 1));
                int l = i | j;
                unsigned long long a = key[i], b = key[l];
                bool desc = ((i & k) == 0);
                if (desc ? (a < b) : (a > b)) { key[i] = b; key[l] = a; }
            }
            __syncthreads();
        }
    }

    if (tid < KMAX) {
        unsigned long long kk = (tid < cnt) ? key[tid] : 0ull;
        bool valid = (tid < cnt) && (kk != 0ull);
        float s = __uint_as_float((unsigned)(kk >> 13));
        int  fi = 8191 - (int)(kk & 8191ull);
        out_scores [n * KMAX + tid] = valid ? s : 0.f;
        out_classes[n * KMAX + tid] = valid ? (float)(fi / KMAX) : 0.f;
        float4 bb = make_float4(0.f, 0.f, 0.f, 0.f);
        if (valid) bb = ((const float4*)g_flat_boxes)[(size_t)n * CK + fi];
        ((float4*)out_boxes)[n * KMAX + tid] = bb;
    }
    if (tid == 0) out_numdets[n] = (float)min(cnt, KMAX);
}

// ---------------------------------------------------------------------------
extern "C" void kernel_launch(void* const* d_in, const int* in_sizes, int n_in,
                              void* d_out, int out_size)
{
    const float* rois   = (const float*)d_in[0];
    const float* conf   = (const float*)d_in[1];
    const float* deltas = (const float*)d_in[2];

    const int rois_elems = in_sizes[0];
    const int N = (out_size - rois_elems) / (6 * KMAX + 1);
    const int B = rois_elems / (4 * N);
    const int C = in_sizes[2] / ((size_t)N * B * 4);
    const int HW = in_sizes[3] / (3 * N);
    const int H = (int)(sqrt((double)HW) + 0.5);   // square image
    const float hm1 = (float)(H - 1);
    const float wm1 = (float)(H - 1);

    float* out         = (float*)d_out;
    float* out_boxes   = out;
    float* out_scores  = out + (size_t)N * KMAX * 4;
    float* out_classes = out + (size_t)N * KMAX * 5;
    float* out_numdets = out + (size_t)N * KMAX * 6;
    float* out_rois    = out + (size_t)N * KMAX * 6 + N;

    {
        dim3 grid((B + 31) / 32, (C + 31) / 32, N);
        dim3 block(32, 8);
        transpose_conf_kernel<<<grid, block>>>(conf, B, C);
    }
    {
        const int NC = N * C;
        decode_nms_kernel<<<(NC + WPB - 1) / WPB, 32 * WPB>>>(
            rois, deltas, B, C, NC, hm1, wm1);
    }
    topk_kernel<<<N, 256>>>(out_boxes, out_scores, out_classes, out_numdets, C);

    cudaMemcpyAsync(out_rois, rois, (size_t)rois_elems * sizeof(float),
                    cudaMemcpyDeviceToDevice, 0);
}

// round 6
// speedup vs baseline: 6.1383x; 1.4139x over previous
#include <cuda_runtime.h>
#include <cmath>

#define KMAX 100
#define NBKT 256
#define WPB  8      // warps per block, one (n,c) problem per warp (2 per SMSP)
#define TRN  128    // tranche size (candidates per NMS round)
#define SPT  4      // candidates per lane (TRN/32)

// Scratch (device globals — no allocation allowed).
__device__ float g_flat_scores[16 * 128 * KMAX];       // [N][C][K]
__device__ float g_flat_boxes [16 * 128 * KMAX * 4];   // [N][C][K][4]
__device__ float g_conf_t     [16 * 128 * 1024];       // [N][C][B] transposed

// ---------------------------------------------------------------------------
// Transpose conf [N][B][C+1] -> g_conf_t [N][C][B]  (drop background column)
// ---------------------------------------------------------------------------
__global__ void transpose_conf_kernel(const float* __restrict__ conf,
                                      int B, int C)
{
    __shared__ float tile[32][33];
    const int n  = blockIdx.z;
    const int b0 = blockIdx.x * 32;
    const int c0 = blockIdx.y * 32;
    const int tx = threadIdx.x, ty = threadIdx.y;   // (32, 8)

    #pragma unroll
    for (int s = 0; s < 4; s++) {
        int b = b0 + ty + s * 8;
        int c = c0 + tx;
        if (b < B && c < C)
            tile[ty + s * 8][tx] = conf[((size_t)n * B + b) * (C + 1) + c];
    }
    __syncthreads();
    #pragma unroll
    for (int s = 0; s < 4; s++) {
        int c = c0 + ty + s * 8;
        int b = b0 + tx;
        if (b < B && c < C)
            g_conf_t[((size_t)n * C + c) * B + b] = tile[tx][ty + s * 8];
    }
}

// ---------------------------------------------------------------------------
// Warp-parallel threshold pickers over a 256-bucket histogram.
// ---------------------------------------------------------------------------
// Maximal window [t_lo, t_hi) with count <= limit (top-down contiguous).
__device__ __forceinline__ int pick_window_le(const unsigned* hist, int t_hi,
                                              int limit, int lane, int* cnt_out)
{
    const unsigned FULL = 0xffffffffu;
    unsigned s = 0;
    #pragma unroll
    for (int m = 0; m < 8; m++) {
        int k = 8 * lane + m;
        if (k < t_hi) s += hist[k];
    }
    unsigned cum = s;                                // suffix-inclusive scan
    #pragma unroll
    for (int off = 1; off < 32; off <<= 1) {
        unsigned o = __shfl_down_sync(FULL, cum, off);
        if (lane + off < 32) cum += o;
    }
    unsigned bal = __ballot_sync(FULL, cum <= (unsigned)limit);
    int t_lo, cnt;
    int l0 = (bal == 0) ? 32 : (__ffs(bal) - 1);
    if (l0 == 0) {
        t_lo = 0;
        cnt  = (int)__shfl_sync(FULL, cum, 0);
    } else {
        int rl = (l0 - 1 < 31) ? l0 - 1 : 31;
        unsigned below = (l0 <= 31) ? __shfl_sync(FULL, cum, l0) : 0u;
        if (l0 == 32) below = 0u;
        int tl = (8 * l0 < 256) ? 8 * l0 : 256;
        unsigned run = below;
        if (lane == rl) {
            #pragma unroll
            for (int m = 7; m >= 0; m--) {
                int k = 8 * rl + m;
                unsigned h = (k < t_hi) ? hist[k] : 0u;
                if (run + h <= (unsigned)limit) { run += h; tl = k; }
                else break;
            }
        }
        t_lo = __shfl_sync(FULL, tl, rl);
        cnt  = (int)__shfl_sync(FULL, run, rl);
    }
    if (t_lo >= t_hi) {          // even one bucket overflows: take it anyway
        t_lo = t_hi - 1;
        cnt  = (int)hist[t_lo];
    }
    *cnt_out = cnt;
    return t_lo;
}

// Minimal window [t_lo, 256) with count >= limit (include boundary-bucket ties).
__device__ __forceinline__ int pick_window_ge(const unsigned* hist, int limit,
                                              int lane, int* cnt_out)
{
    const unsigned FULL = 0xffffffffu;
    unsigned s = 0;
    #pragma unroll
    for (int m = 0; m < 8; m++) s += hist[8 * lane + m];
    unsigned cum = s;
    #pragma unroll
    for (int off = 1; off < 32; off <<= 1) {
        unsigned o = __shfl_down_sync(FULL, cum, off);
        if (lane + off < 32) cum += o;
    }
    unsigned bal = __ballot_sync(FULL, cum >= (unsigned)limit);
    int t_lo, cnt;
    if (bal == 0) {                       // fewer than limit valid total
        t_lo = 0;
        cnt  = (int)__shfl_sync(FULL, cum, 0);
    } else {
        int lp = 31 - __clz(bal);         // highest lane with suffix >= limit
        unsigned below = (lp < 31) ? __shfl_sync(FULL, cum, lp + 1) : 0u;
        int tl = 8 * (lp + 1);
        unsigned run = below;
        if (lane == lp) {
            #pragma unroll
            for (int m = 7; m >= 0; m--) {
                run += hist[8 * lp + m];
                tl = 8 * lp + m;
                if (run >= (unsigned)limit) break;
            }
        }
        t_lo = __shfl_sync(FULL, tl, lp);
        cnt  = (int)__shfl_sync(FULL, run, lp);
    }
    *cnt_out = cnt;
    return t_lo;
}

// ---------------------------------------------------------------------------
// Stage 1: one WARP per (n, c); 8 warps per 256-thread CTA (2 per SMSP for
// latency hiding; grid = 80 <= 148 SMs, single wave). Per-warp smem slices.
// score load -> histogram -> threshold -> ballot compact (<=128) ->
// bitonic sort -> gather-decode -> greedy NMS (division-free IoU predicate).
// ---------------------------------------------------------------------------
__global__ __launch_bounds__(32 * WPB)
void decode_nms_kernel(const float* __restrict__ rois,
                       const float* __restrict__ deltas,
                       int B, int C, int NC, float hm1, float wm1)
{
    const int w    = threadIdx.x >> 5;
    const int lane = threadIdx.x & 31;
    const int pid  = blockIdx.x * WPB + w;
    if (pid >= NC) return;
    const int n = pid / C;
    const int c = pid % C;
    const unsigned FULL = 0xffffffffu;

    __shared__ unsigned           hist_s [WPB][NBKT];
    __shared__ unsigned long long ckey_s [WPB][TRN];
    __shared__ float4             rbox_s [WPB][TRN];
    __shared__ float              rarea_s[WPB][TRN];

    unsigned*           hist  = hist_s [w];
    unsigned long long* ckey  = ckey_s [w];
    float4*             rbox  = rbox_s [w];
    float*              rarea = rarea_s[w];

    for (int i = lane; i < NBKT; i += 32) hist[i] = 0u;
    __syncwarp();

    // ---- coalesced score load (transposed conf), MLP=8 ----
    const float* csrc = g_conf_t + ((size_t)n * C + c) * B;
    const int NV4 = B >> 2;          // B divisible by 4 (B=1000)
    float rs[32];
    #pragma unroll
    for (int u = 0; u < 8; u++) {
        int i4 = lane + 32 * u;
        float4 v = make_float4(0.f, 0.f, 0.f, 0.f);
        if (i4 < NV4) v = ((const float4*)csrc)[i4];
        rs[4*u+0] = (v.x > 0.05f) ? v.x : 0.f;
        rs[4*u+1] = (v.y > 0.05f) ? v.y : 0.f;
        rs[4*u+2] = (v.z > 0.05f) ? v.z : 0.f;
        rs[4*u+3] = (v.w > 0.05f) ? v.w : 0.f;
    }
    // b index of rs[e]: e = 4u + j  ->  b = 128*u + 4*lane + j

    #pragma unroll
    for (int e = 0; e < 32; e++) {
        float v = rs[e];
        if (v > 0.f) atomicAdd(&hist[min((int)(v * 256.f), 255)], 1u);
    }
    __syncwarp();

    float* fs = g_flat_scores + ((size_t)n * C + c) * KMAX;
    float* fb = g_flat_boxes  + ((size_t)n * C + c) * KMAX * 4;

    int kept = 0;
    int t_hi = NBKT;

    while (kept < KMAX && t_hi > 0) {
        int cnt;
        const int t_lo = pick_window_le(hist, t_hi, TRN, lane, &cnt);
        const int w_hi = t_hi;          // window = [t_lo, w_hi)
        t_hi = t_lo;
        if (cnt > TRN) cnt = TRN;
        if (cnt == 0) continue;

        // ---- ballot compaction ----
        unsigned base = 0;
        #pragma unroll
        for (int e = 0; e < 32; e++) {
            float v = rs[e];
            int bk = (v > 0.f) ? min((int)(v * 256.f), 255) : -1;
            bool take = (bk >= t_lo) && (bk < w_hi);
            unsigned m = __ballot_sync(FULL, take);
            if (take) {
                unsigned pos = base + __popc(m & ((1u << lane) - 1u));
                if (pos < (unsigned)TRN) {
                    int b = 128 * (e >> 2) + 4 * lane + (e & 3);
                    ckey[pos] = ((unsigned long long)__float_as_uint(v) << 10)
                              | (unsigned long long)(1023 - b);
                }
            }
            base += __popc(m);
        }
        __syncwarp();

        int P = 1; while (P < cnt) P <<= 1;
        for (int i = cnt + lane; i < P; i += 32) ckey[i] = 0ull;
        __syncwarp();

        // ---- bitonic sort desc by (score, ~b) ----
        for (int k = 2; k <= P; k <<= 1) {
            for (int j = k >> 1; j > 0; j >>= 1) {
                for (int p = lane; p < (P >> 1); p += 32) {
                    int i = ((p & ~(j - 1)) << 1) | (p & (j - 1));
                    int l = i | j;
                    unsigned long long a = ckey[i], bb = ckey[l];
                    bool desc = ((i & k) == 0);
                    if (desc ? (a < bb) : (a > bb)) { ckey[i] = bb; ckey[l] = a; }
                }
                __syncwarp();
            }
        }

        // ---- gather-decode (blocked ranks: lane owns SPT*lane..SPT*lane+3) --
        float by1[SPT], bx1[SPT], by2[SPT], bx2[SPT], bar_[SPT];
        unsigned alive = 0;
        #pragma unroll
        for (int q = 0; q < SPT; q++) {
            int r = SPT * lane + q;
            float yy1 = 0.f, xx1 = 0.f, yy2 = 0.f, xx2 = 0.f, ar = 0.f;
            if (r < cnt) {
                unsigned long long key = ckey[r];
                int b = 1023 - (int)(key & 1023ull);
                float4 rr = ((const float4*)rois)[(size_t)n * B + b];
                float w0 = rr.w - rr.y + 1.0f;
                float h0 = rr.z - rr.x + 1.0f;
                float x0 = rr.y + 0.5f * w0;
                float y0 = rr.x + 0.5f * h0;
                float4 d = ((const float4*)deltas)[((size_t)n * B + b) * C + c];
                float cx = (d.x * 0.1f) * w0 + x0;
                float cy = (d.y * 0.1f) * h0 + y0;
                float ww = __expf(d.z * 0.2f) * w0;
                float hh = __expf(d.w * 0.2f) * h0;
                xx1 = fminf(fmaxf(cx - 0.5f * ww, 0.0f), wm1);
                yy1 = fminf(fmaxf(cy - 0.5f * hh, 0.0f), hm1);
                xx2 = fminf(fmaxf(cx + 0.5f * ww, 0.0f), wm1);
                yy2 = fminf(fmaxf(cy + 0.5f * hh, 0.0f), hm1);
                ar  = (yy2 - yy1) * (xx2 - xx1);
                rbox[r]  = make_float4(yy1, xx1, yy2, xx2);
                rarea[r] = ar;
                alive |= (1u << q);
            }
            by1[q] = yy1; bx1[q] = xx1; by2[q] = yy2; bx2[q] = xx2; bar_[q] = ar;
        }
        __syncwarp();

        // ---- later tranches: pre-suppress vs already-kept boxes ----
        for (int kk = 0; kk < kept; kk++) {
            float4 kb = ((const float4*)fb)[kk];
            float ka = (kb.z - kb.x) * (kb.w - kb.y);
            #pragma unroll
            for (int q = 0; q < SPT; q++) {
                if (alive & (1u << q)) {
                    float iy1 = fmaxf(kb.x, by1[q]);
                    float ix1 = fmaxf(kb.y, bx1[q]);
                    float iy2 = fminf(kb.z, by2[q]);
                    float ix2 = fminf(kb.w, bx2[q]);
                    float it  = fmaxf(iy2 - iy1, 0.f) * fmaxf(ix2 - ix1, 0.f);
                    float un  = fmaxf(ka + bar_[q] - it, 1e-8f);
                    if (it > 0.5f * un) alive &= ~(1u << q);
                }
            }
        }

        // ---- greedy NMS sweep (division-free) ----
        while (kept < KMAX) {
            unsigned my = alive ? (unsigned)(SPT * lane + __ffs(alive) - 1)
                                : (unsigned)TRN;
            unsigned R = __reduce_min_sync(FULL, my);
            if (R >= (unsigned)TRN) break;

            float4 bb = rbox[R];
            float  ba = rarea[R];
            if ((int)(R / SPT) == lane) alive &= ~(1u << (R % SPT));
            if (lane == 0) {
                fs[kept] = __uint_as_float((unsigned)(ckey[R] >> 10));
                ((float4*)fb)[kept] = bb;
            }
            kept++;

            if (alive) {
                #pragma unroll
                for (int q = 0; q < SPT; q++) {
                    if (alive & (1u << q)) {
                        float iy1 = fmaxf(bb.x, by1[q]);
                        float ix1 = fmaxf(bb.y, bx1[q]);
                        float iy2 = fminf(bb.z, by2[q]);
                        float ix2 = fminf(bb.w, bx2[q]);
                        float it  = fmaxf(iy2 - iy1, 0.f) * fmaxf(ix2 - ix1, 0.f);
                        float un  = fmaxf(ba + bar_[q] - it, 1e-8f);
                        if (it > 0.5f * un) alive &= ~(1u << q);
                    }
                }
            }
        }
        __syncwarp();
    }

    for (int kk = kept + lane; kk < KMAX; kk += 32) fs[kk] = 0.0f;
}

// ---------------------------------------------------------------------------
// Stage 2: per image, exact rank-100 via batched loads + histogram + sort.
// ---------------------------------------------------------------------------
__global__ __launch_bounds__(256)
void topk_kernel(float* __restrict__ out_boxes,
                 float* __restrict__ out_scores,
                 float* __restrict__ out_classes,
                 float* __restrict__ out_numdets,
                 int C)
{
    const int n    = blockIdx.x;
    const int tid  = threadIdx.x;
    const int lane = tid & 31;
    const int CK   = C * KMAX;                 // 8000

    __shared__ unsigned           hist[NBKT];
    __shared__ unsigned long long key[1024];
    __shared__ unsigned           scnt;

    for (int i = tid; i < NBKT; i += 256) hist[i] = 0u;
    if (tid == 0) scnt = 0u;
    __syncthreads();

    // batched register loads, MLP=8
    const float* src = g_flat_scores + (size_t)n * CK;
    const int NV4 = CK >> 2;
    float4 v4[8];
    #pragma unroll
    for (int u = 0; u < 8; u++) {
        int i4 = tid + 256 * u;
        v4[u] = (i4 < NV4) ? ((const float4*)src)[i4]
                           : make_float4(0.f, 0.f, 0.f, 0.f);
    }
    #pragma unroll
    for (int u = 0; u < 8; u++) {
        float vv[4] = {v4[u].x, v4[u].y, v4[u].z, v4[u].w};
        #pragma unroll
        for (int j = 0; j < 4; j++)
            if (vv[j] > 0.f)
                atomicAdd(&hist[min((int)(vv[j] * 256.f), 255)], 1u);
    }
    __syncthreads();

    int cnt_est;
    const int t_lo = pick_window_ge(hist, KMAX, lane, &cnt_est);  // all warps same

    #pragma unroll
    for (int u = 0; u < 8; u++) {
        float vv[4] = {v4[u].x, v4[u].y, v4[u].z, v4[u].w};
        #pragma unroll
        for (int j = 0; j < 4; j++) {
            float v = vv[j];
            if (v > 0.f && min((int)(v * 256.f), 255) >= t_lo) {
                unsigned p = atomicAdd(&scnt, 1u);
                if (p < 1024u) {
                    int i = 4 * (tid + 256 * u) + j;
                    key[p] = ((unsigned long long)__float_as_uint(v) << 13)
                           | (unsigned long long)(8191 - i);
                }
            }
        }
    }
    __syncthreads();
    const int cnt = min((int)scnt, 1024);

    int P = 2; while (P < cnt) P <<= 1;
    for (int i = cnt + tid; i < P; i += 256) key[i] = 0ull;
    __syncthreads();

    for (int k = 2; k <= P; k <<= 1) {
        for (int j = k >> 1; j > 0; j >>= 1) {
            for (int p = tid; p < (P >> 1); p += 256) {
                int i = ((p & ~(j - 1)) << 1) | (p & (j - 1));
                int l = i | j;
                unsigned long long a = key[i], b = key[l];
                bool desc = ((i & k) == 0);
                if (desc ? (a < b) : (a > b)) { key[i] = b; key[l] = a; }
            }
            __syncthreads();
        }
    }

    if (tid < KMAX) {
        unsigned long long kk = (tid < cnt) ? key[tid] : 0ull;
        bool valid = (tid < cnt) && (kk != 0ull);
        float s = __uint_as_float((unsigned)(kk >> 13));
        int  fi = 8191 - (int)(kk & 8191ull);
        out_scores [n * KMAX + tid] = valid ? s : 0.f;
        out_classes[n * KMAX + tid] = valid ? (float)(fi / KMAX) : 0.f;
        float4 bb = make_float4(0.f, 0.f, 0.f, 0.f);
        if (valid) bb = ((const float4*)g_flat_boxes)[(size_t)n * CK + fi];
        ((float4*)out_boxes)[n * KMAX + tid] = bb;
    }
    if (tid == 0) out_numdets[n] = (float)min(cnt, KMAX);
}

// ---------------------------------------------------------------------------
extern "C" void kernel_launch(void* const* d_in, const int* in_sizes, int n_in,
                              void* d_out, int out_size)
{
    const float* rois   = (const float*)d_in[0];
    const float* conf   = (const float*)d_in[1];
    const float* deltas = (const float*)d_in[2];

    const int rois_elems = in_sizes[0];
    const int N = (out_size - rois_elems) / (6 * KMAX + 1);
    const int B = rois_elems / (4 * N);
    const int C = in_sizes[2] / ((size_t)N * B * 4);
    const int HW = in_sizes[3] / (3 * N);
    const int H = (int)(sqrt((double)HW) + 0.5);   // square image
    const float hm1 = (float)(H - 1);
    const float wm1 = (float)(H - 1);

    float* out         = (float*)d_out;
    float* out_boxes   = out;
    float* out_scores  = out + (size_t)N * KMAX * 4;
    float* out_classes = out + (size_t)N * KMAX * 5;
    float* out_numdets = out + (size_t)N * KMAX * 6;
    float* out_rois    = out + (size_t)N * KMAX * 6 + N;

    {
        dim3 grid((B + 31) / 32, (C + 31) / 32, N);
        dim3 block(32, 8);
        transpose_conf_kernel<<<grid, block>>>(conf, B, C);
    }
    {
        const int NC = N * C;
        decode_nms_kernel<<<(NC + WPB - 1) / WPB, 32 * WPB>>>(
            rois, deltas, B, C, NC, hm1, wm1);
    }
    topk_kernel<<<N, 256>>>(out_boxes, out_scores, out_classes, out_numdets, C);

    cudaMemcpyAsync(out_rois, rois, (size_t)rois_elems * sizeof(float),
                    cudaMemcpyDeviceToDevice, 0);
}

// round 7
// speedup vs baseline: 8.2819x; 1.3492x over previous
#include <cuda_runtime.h>
#include <cmath>

#define KMAX 100
#define NBKT 256
#define WPB  8      // warps per block, one (n,c) problem per warp (2 per SMSP)
#define TRN  128    // tranche size (candidates per NMS round)
#define SPT  4      // candidates per lane (TRN/32)

// Scratch (device globals — no allocation allowed).
__device__ float g_flat_scores[16 * 128 * KMAX];       // [N][C][K]
__device__ float g_flat_boxes [16 * 128 * KMAX * 4];   // [N][C][K][4]
__device__ float g_conf_t     [16 * 128 * 1024];       // [N][C][B] transposed

// ---------------------------------------------------------------------------
// Transpose conf [N][B][C+1] -> g_conf_t [N][C][B]  (drop background column)
// ---------------------------------------------------------------------------
__global__ void transpose_conf_kernel(const float* __restrict__ conf,
                                      int B, int C)
{
    __shared__ float tile[32][33];
    const int n  = blockIdx.z;
    const int b0 = blockIdx.x * 32;
    const int c0 = blockIdx.y * 32;
    const int tx = threadIdx.x, ty = threadIdx.y;   // (32, 8)

    #pragma unroll
    for (int s = 0; s < 4; s++) {
        int b = b0 + ty + s * 8;
        int c = c0 + tx;
        if (b < B && c < C)
            tile[ty + s * 8][tx] = conf[((size_t)n * B + b) * (C + 1) + c];
    }
    __syncthreads();
    #pragma unroll
    for (int s = 0; s < 4; s++) {
        int c = c0 + ty + s * 8;
        int b = b0 + tx;
        if (b < B && c < C)
            g_conf_t[((size_t)n * C + c) * B + b] = tile[tx][ty + s * 8];
    }
}

// ---------------------------------------------------------------------------
// Warp-parallel threshold pickers over a 256-bucket histogram.
// ---------------------------------------------------------------------------
// Maximal window [t_lo, t_hi) with count <= limit (top-down contiguous).
__device__ __forceinline__ int pick_window_le(const unsigned* hist, int t_hi,
                                              int limit, int lane, int* cnt_out)
{
    const unsigned FULL = 0xffffffffu;
    unsigned s = 0;
    #pragma unroll
    for (int m = 0; m < 8; m++) {
        int k = 8 * lane + m;
        if (k < t_hi) s += hist[k];
    }
    unsigned cum = s;                                // suffix-inclusive scan
    #pragma unroll
    for (int off = 1; off < 32; off <<= 1) {
        unsigned o = __shfl_down_sync(FULL, cum, off);
        if (lane + off < 32) cum += o;
    }
    unsigned bal = __ballot_sync(FULL, cum <= (unsigned)limit);
    int t_lo, cnt;
    int l0 = (bal == 0) ? 32 : (__ffs(bal) - 1);
    if (l0 == 0) {
        t_lo = 0;
        cnt  = (int)__shfl_sync(FULL, cum, 0);
    } else {
        int rl = (l0 - 1 < 31) ? l0 - 1 : 31;
        unsigned below = (l0 <= 31) ? __shfl_sync(FULL, cum, l0) : 0u;
        if (l0 == 32) below = 0u;
        int tl = (8 * l0 < 256) ? 8 * l0 : 256;
        unsigned run = below;
        if (lane == rl) {
            #pragma unroll
            for (int m = 7; m >= 0; m--) {
                int k = 8 * rl + m;
                unsigned h = (k < t_hi) ? hist[k] : 0u;
                if (run + h <= (unsigned)limit) { run += h; tl = k; }
                else break;
            }
        }
        t_lo = __shfl_sync(FULL, tl, rl);
        cnt  = (int)__shfl_sync(FULL, run, rl);
    }
    if (t_lo >= t_hi) {          // even one bucket overflows: take it anyway
        t_lo = t_hi - 1;
        cnt  = (int)hist[t_lo];
    }
    *cnt_out = cnt;
    return t_lo;
}

// Minimal window [t_lo, 256) with count >= limit (include boundary-bucket ties).
__device__ __forceinline__ int pick_window_ge(const unsigned* hist, int limit,
                                              int lane, int* cnt_out)
{
    const unsigned FULL = 0xffffffffu;
    unsigned s = 0;
    #pragma unroll
    for (int m = 0; m < 8; m++) s += hist[8 * lane + m];
    unsigned cum = s;
    #pragma unroll
    for (int off = 1; off < 32; off <<= 1) {
        unsigned o = __shfl_down_sync(FULL, cum, off);
        if (lane + off < 32) cum += o;
    }
    unsigned bal = __ballot_sync(FULL, cum >= (unsigned)limit);
    int t_lo, cnt;
    if (bal == 0) {                       // fewer than limit valid total
        t_lo = 0;
        cnt  = (int)__shfl_sync(FULL, cum, 0);
    } else {
        int lp = 31 - __clz(bal);         // highest lane with suffix >= limit
        unsigned below = (lp < 31) ? __shfl_sync(FULL, cum, lp + 1) : 0u;
        int tl = 8 * (lp + 1);
        unsigned run = below;
        if (lane == lp) {
            #pragma unroll
            for (int m = 7; m >= 0; m--) {
                run += hist[8 * lp + m];
                tl = 8 * lp + m;
                if (run >= (unsigned)limit) break;
            }
        }
        t_lo = __shfl_sync(FULL, tl, lp);
        cnt  = (int)__shfl_sync(FULL, run, lp);
    }
    *cnt_out = cnt;
    return t_lo;
}

// ---------------------------------------------------------------------------
// Stage 1: one WARP per (n, c); 8 warps per 256-thread CTA.
// score load -> histogram -> threshold -> ballot compact (<=128) ->
// bitonic sort -> gather-decode -> PAIRWISE suppression-mask matrix (throughput
// bound, deep ILP) -> single-lane serial bit-scan (short latency chain) ->
// parallel output epilogue.
// ---------------------------------------------------------------------------
__global__ __launch_bounds__(32 * WPB)
void decode_nms_kernel(const float* __restrict__ rois,
                       const float* __restrict__ deltas,
                       int B, int C, int NC, float hm1, float wm1)
{
    const int w    = threadIdx.x >> 5;
    const int lane = threadIdx.x & 31;
    const int pid  = blockIdx.x * WPB + w;
    if (pid >= NC) return;
    const int n = pid / C;
    const int c = pid % C;
    const unsigned FULL = 0xffffffffu;

    __shared__ unsigned           hist_s [WPB][NBKT];
    __shared__ unsigned long long ckey_s [WPB][TRN];
    __shared__ float4             rbox_s [WPB][TRN];
    __shared__ float              rarea_s[WPB][TRN];
    __shared__ uint4              mask_s [WPB][TRN];
    __shared__ float4             kbox_s [WPB][KMAX];
    __shared__ float              karea_s[WPB][KMAX];
    __shared__ int                sidx_s [WPB][KMAX];

    unsigned*           hist  = hist_s [w];
    unsigned long long* ckey  = ckey_s [w];
    float4*             rbox  = rbox_s [w];
    float*              rarea = rarea_s[w];
    uint4*              maskm = mask_s [w];
    float4*             kbox  = kbox_s [w];
    float*              karea = karea_s[w];
    int*                sidx  = sidx_s [w];

    for (int i = lane; i < NBKT; i += 32) hist[i] = 0u;
    __syncwarp();

    // ---- coalesced score load (transposed conf), MLP=8 ----
    const float* csrc = g_conf_t + ((size_t)n * C + c) * B;
    const int NV4 = B >> 2;          // B divisible by 4 (B=1000)
    float rs[32];
    #pragma unroll
    for (int u = 0; u < 8; u++) {
        int i4 = lane + 32 * u;
        float4 v = make_float4(0.f, 0.f, 0.f, 0.f);
        if (i4 < NV4) v = ((const float4*)csrc)[i4];
        rs[4*u+0] = (v.x > 0.05f) ? v.x : 0.f;
        rs[4*u+1] = (v.y > 0.05f) ? v.y : 0.f;
        rs[4*u+2] = (v.z > 0.05f) ? v.z : 0.f;
        rs[4*u+3] = (v.w > 0.05f) ? v.w : 0.f;
    }
    // b index of rs[e]: e = 4u + j  ->  b = 128*u + 4*lane + j

    #pragma unroll
    for (int e = 0; e < 32; e++) {
        float v = rs[e];
        if (v > 0.f) atomicAdd(&hist[min((int)(v * 256.f), 255)], 1u);
    }
    __syncwarp();

    float* fs = g_flat_scores + ((size_t)n * C + c) * KMAX;
    float* fb = g_flat_boxes  + ((size_t)n * C + c) * KMAX * 4;

    int kept = 0;
    int t_hi = NBKT;

    while (kept < KMAX && t_hi > 0) {
        int cnt;
        const int t_lo = pick_window_le(hist, t_hi, TRN, lane, &cnt);
        const int w_hi = t_hi;          // window = [t_lo, w_hi)
        t_hi = t_lo;
        if (cnt > TRN) cnt = TRN;
        if (cnt == 0) continue;

        // ---- ballot compaction ----
        unsigned base = 0;
        #pragma unroll
        for (int e = 0; e < 32; e++) {
            float v = rs[e];
            int bk = (v > 0.f) ? min((int)(v * 256.f), 255) : -1;
            bool take = (bk >= t_lo) && (bk < w_hi);
            unsigned m = __ballot_sync(FULL, take);
            if (take) {
                unsigned pos = base + __popc(m & ((1u << lane) - 1u));
                if (pos < (unsigned)TRN) {
                    int b = 128 * (e >> 2) + 4 * lane + (e & 3);
                    ckey[pos] = ((unsigned long long)__float_as_uint(v) << 10)
                              | (unsigned long long)(1023 - b);
                }
            }
            base += __popc(m);
        }
        __syncwarp();

        int P = 1; while (P < cnt) P <<= 1;
        for (int i = cnt + lane; i < P; i += 32) ckey[i] = 0ull;
        __syncwarp();

        // ---- bitonic sort desc by (score, ~b) ----
        for (int k = 2; k <= P; k <<= 1) {
            for (int j = k >> 1; j > 0; j >>= 1) {
                for (int p = lane; p < (P >> 1); p += 32) {
                    int i = ((p & ~(j - 1)) << 1) | (p & (j - 1));
                    int l = i | j;
                    unsigned long long a = ckey[i], bb = ckey[l];
                    bool desc = ((i & k) == 0);
                    if (desc ? (a < bb) : (a > bb)) { ckey[i] = bb; ckey[l] = a; }
                }
                __syncwarp();
            }
        }

        // ---- gather-decode (blocked ranks: lane owns 4*lane..4*lane+3) ----
        float by1[SPT], bx1[SPT], by2[SPT], bx2[SPT], bar_[SPT];
        unsigned alive = 0;
        #pragma unroll
        for (int q = 0; q < SPT; q++) {
            int r = SPT * lane + q;
            float yy1 = 0.f, xx1 = 0.f, yy2 = 0.f, xx2 = 0.f, ar = 0.f;
            if (r < cnt) {
                unsigned long long key = ckey[r];
                int b = 1023 - (int)(key & 1023ull);
                float4 rr = ((const float4*)rois)[(size_t)n * B + b];
                float w0 = rr.w - rr.y + 1.0f;
                float h0 = rr.z - rr.x + 1.0f;
                float x0 = rr.y + 0.5f * w0;
                float y0 = rr.x + 0.5f * h0;
                float4 d = ((const float4*)deltas)[((size_t)n * B + b) * C + c];
                float cx = (d.x * 0.1f) * w0 + x0;
                float cy = (d.y * 0.1f) * h0 + y0;
                float ww = __expf(d.z * 0.2f) * w0;
                float hh = __expf(d.w * 0.2f) * h0;
                xx1 = fminf(fmaxf(cx - 0.5f * ww, 0.0f), wm1);
                yy1 = fminf(fmaxf(cy - 0.5f * hh, 0.0f), hm1);
                xx2 = fminf(fmaxf(cx + 0.5f * ww, 0.0f), wm1);
                yy2 = fminf(fmaxf(cy + 0.5f * hh, 0.0f), hm1);
                ar  = (yy2 - yy1) * (xx2 - xx1);
                rbox[r]  = make_float4(yy1, xx1, yy2, xx2);
                rarea[r] = ar;
                alive |= (1u << q);
            }
            by1[q] = yy1; bx1[q] = xx1; by2[q] = yy2; bx2[q] = xx2; bar_[q] = ar;
        }
        __syncwarp();

        // ---- later tranches: pre-suppress vs already-kept boxes ----
        for (int kk = 0; kk < kept; kk++) {
            float4 kb = kbox[kk];
            float  ka = karea[kk];
            #pragma unroll
            for (int q = 0; q < SPT; q++) {
                if (alive & (1u << q)) {
                    float iy1 = fmaxf(kb.x, by1[q]);
                    float ix1 = fmaxf(kb.y, bx1[q]);
                    float iy2 = fminf(kb.z, by2[q]);
                    float ix2 = fminf(kb.w, bx2[q]);
                    float it  = fmaxf(iy2 - iy1, 0.f) * fmaxf(ix2 - ix1, 0.f);
                    float un  = fmaxf(ka + bar_[q] - it, 1e-8f);
                    if (it > 0.5f * un) alive &= ~(1u << q);
                }
            }
        }

        // ---- pairwise suppression-mask matrix (throughput-bound, deep ILP) --
        // Lane L builds rows for candidates r = 4L+q; bit s set iff IoU>thres
        // (self-bit forced so the scan needs no special zero-area handling).
        const int wmax = (cnt + 31) >> 5;
        for (int wb = 0; wb < wmax; wb++) {
            unsigned acc0 = 0, acc1 = 0, acc2 = 0, acc3 = 0;
            #pragma unroll 8
            for (int sb = 0; sb < 32; sb++) {
                int s = 32 * wb + sb;
                float4 bs = rbox[s];          // broadcast LDS
                float  as_ = rarea[s];
                #pragma unroll
                for (int q = 0; q < SPT; q++) {
                    float iy1 = fmaxf(bs.x, by1[q]);
                    float ix1 = fmaxf(bs.y, bx1[q]);
                    float iy2 = fminf(bs.z, by2[q]);
                    float ix2 = fminf(bs.w, bx2[q]);
                    float it  = fmaxf(iy2 - iy1, 0.f) * fmaxf(ix2 - ix1, 0.f);
                    float un  = fmaxf(as_ + bar_[q] - it, 1e-8f);
                    unsigned bit = (it > 0.5f * un) ? (1u << sb) : 0u;
                    if (q == 0) acc0 |= bit;
                    else if (q == 1) acc1 |= bit;
                    else if (q == 2) acc2 |= bit;
                    else acc3 |= bit;
                }
            }
            // force self-bits
            #pragma unroll
            for (int q = 0; q < SPT; q++) {
                int r = SPT * lane + q;
                unsigned sb_ = ((r >> 5) == wb) ? (1u << (r & 31)) : 0u;
                if (q == 0) acc0 |= sb_;
                else if (q == 1) acc1 |= sb_;
                else if (q == 2) acc2 |= sb_;
                else acc3 |= sb_;
            }
            ((unsigned*)&maskm[SPT * lane + 0])[wb] = acc0;
            ((unsigned*)&maskm[SPT * lane + 1])[wb] = acc1;
            ((unsigned*)&maskm[SPT * lane + 2])[wb] = acc2;
            ((unsigned*)&maskm[SPT * lane + 3])[wb] = acc3;
        }
        __syncwarp();

        // ---- assemble 128-bit alive vector on lane 0 ----
        unsigned a0 = 0, a1 = 0, a2 = 0, a3 = 0;
        for (int L = 0; L < 32; L++) {
            unsigned nib = __shfl_sync(FULL, alive, L);
            if (lane == 0) {
                unsigned sh = (unsigned)((L & 7) * 4);
                if (L < 8)       a0 |= nib << sh;
                else if (L < 16) a1 |= nib << sh;
                else if (L < 24) a2 |= nib << sh;
                else             a3 |= nib << sh;
            }
        }

        // ---- serial bit-scan on lane 0 (short chain: ffs -> LDS -> AND) ----
        int kn = 0;
        if (lane == 0) {
            const int room = KMAX - kept;
            while (kn < room) {
                int r;
                if (a0)      r = __ffs(a0) - 1;
                else if (a1) r = 31 + __ffs(a1);
                else if (a2) r = 63 + __ffs(a2);
                else if (a3) r = 95 + __ffs(a3);
                else break;
                sidx[kn++] = r;
                uint4 m = maskm[r];        // LDS.128 (has self-bit)
                a0 &= ~m.x; a1 &= ~m.y; a2 &= ~m.z; a3 &= ~m.w;
            }
        }
        kn = __shfl_sync(FULL, kn, 0);

        // ---- parallel output epilogue ----
        for (int i = lane; i < kn; i += 32) {
            int r = sidx[i];
            float4 bb = rbox[r];
            fs[kept + i] = __uint_as_float((unsigned)(ckey[r] >> 10));
            ((float4*)fb)[kept + i] = bb;
            kbox[kept + i]  = bb;
            karea[kept + i] = rarea[r];
        }
        kept += kn;
        __syncwarp();
    }

    for (int kk = kept + lane; kk < KMAX; kk += 32) fs[kk] = 0.0f;
}

// ---------------------------------------------------------------------------
// Stage 2: per image, exact rank-100 via batched loads + histogram + sort.
// ---------------------------------------------------------------------------
__global__ __launch_bounds__(256)
void topk_kernel(float* __restrict__ out_boxes,
                 float* __restrict__ out_scores,
                 float* __restrict__ out_classes,
                 float* __restrict__ out_numdets,
                 int C)
{
    const int n    = blockIdx.x;
    const int tid  = threadIdx.x;
    const int lane = tid & 31;
    const int CK   = C * KMAX;                 // 8000

    __shared__ unsigned           hist[NBKT];
    __shared__ unsigned long long key[1024];
    __shared__ unsigned           scnt;

    for (int i = tid; i < NBKT; i += 256) hist[i] = 0u;
    if (tid == 0) scnt = 0u;
    __syncthreads();

    // batched register loads, MLP=8
    const float* src = g_flat_scores + (size_t)n * CK;
    const int NV4 = CK >> 2;
    float4 v4[8];
    #pragma unroll
    for (int u = 0; u < 8; u++) {
        int i4 = tid + 256 * u;
        v4[u] = (i4 < NV4) ? ((const float4*)src)[i4]
                           : make_float4(0.f, 0.f, 0.f, 0.f);
    }
    #pragma unroll
    for (int u = 0; u < 8; u++) {
        float vv[4] = {v4[u].x, v4[u].y, v4[u].z, v4[u].w};
        #pragma unroll
        for (int j = 0; j < 4; j++)
            if (vv[j] > 0.f)
                atomicAdd(&hist[min((int)(vv[j] * 256.f), 255)], 1u);
    }
    __syncthreads();

    int cnt_est;
    const int t_lo = pick_window_ge(hist, KMAX, lane, &cnt_est);  // all warps same

    #pragma unroll
    for (int u = 0; u < 8; u++) {
        float vv[4] = {v4[u].x, v4[u].y, v4[u].z, v4[u].w};
        #pragma unroll
        for (int j = 0; j < 4; j++) {
            float v = vv[j];
            if (v > 0.f && min((int)(v * 256.f), 255) >= t_lo) {
                unsigned p = atomicAdd(&scnt, 1u);
                if (p < 1024u) {
                    int i = 4 * (tid + 256 * u) + j;
                    key[p] = ((unsigned long long)__float_as_uint(v) << 13)
                           | (unsigned long long)(8191 - i);
                }
            }
        }
    }
    __syncthreads();
    const int cnt = min((int)scnt, 1024);

    int P = 2; while (P < cnt) P <<= 1;
    for (int i = cnt + tid; i < P; i += 256) key[i] = 0ull;
    __syncthreads();

    for (int k = 2; k <= P; k <<= 1) {
        for (int j = k >> 1; j > 0; j >>= 1) {
            for (int p = tid; p < (P >> 1); p += 256) {
                int i = ((p & ~(j - 1)) << 1) | (p & (j - 1));
                int l = i | j;
                unsigned long long a = key[i], b = key[l];
                bool desc = ((i & k) == 0);
                if (desc ? (a < b) : (a > b)) { key[i] = b; key[l] = a; }
            }
            __syncthreads();
        }
    }

    if (tid < KMAX) {
        unsigned long long kk = (tid < cnt) ? key[tid] : 0ull;
        bool valid = (tid < cnt) && (kk != 0ull);
        float s = __uint_as_float((unsigned)(kk >> 13));
        int  fi = 8191 - (int)(kk & 8191ull);
        out_scores [n * KMAX + tid] = valid ? s : 0.f;
        out_classes[n * KMAX + tid] = valid ? (float)(fi / KMAX) : 0.f;
        float4 bb = make_float4(0.f, 0.f, 0.f, 0.f);
        if (valid) bb = ((const float4*)g_flat_boxes)[(size_t)n * CK + fi];
        ((float4*)out_boxes)[n * KMAX + tid] = bb;
    }
    if (tid == 0) out_numdets[n] = (float)min(cnt, KMAX);
}

// ---------------------------------------------------------------------------
extern "C" void kernel_launch(void* const* d_in, const int* in_sizes, int n_in,
                              void* d_out, int out_size)
{
    const float* rois   = (const float*)d_in[0];
    const float* conf   = (const float*)d_in[1];
    const float* deltas = (const float*)d_in[2];

    const int rois_elems = in_sizes[0];
    const int N = (out_size - rois_elems) / (6 * KMAX + 1);
    const int B = rois_elems / (4 * N);
    const int C = in_sizes[2] / ((size_t)N * B * 4);
    const int HW = in_sizes[3] / (3 * N);
    const int H = (int)(sqrt((double)HW) + 0.5);   // square image
    const float hm1 = (float)(H - 1);
    const float wm1 = (float)(H - 1);

    float* out         = (float*)d_out;
    float* out_boxes   = out;
    float* out_scores  = out + (size_t)N * KMAX * 4;
    float* out_classes = out + (size_t)N * KMAX * 5;
    float* out_numdets = out + (size_t)N * KMAX * 6;
    float* out_rois    = out + (size_t)N * KMAX * 6 + N;

    {
        dim3 grid((B + 31) / 32, (C + 31) / 32, N);
        dim3 block(32, 8);
        transpose_conf_kernel<<<grid, block>>>(conf, B, C);
    }
    {
        const int NC = N * C;
        decode_nms_kernel<<<(NC + WPB - 1) / WPB, 32 * WPB>>>(
            rois, deltas, B, C, NC, hm1, wm1);
    }
    topk_kernel<<<N, 256>>>(out_boxes, out_scores, out_classes, out_numdets, C);

    cudaMemcpyAsync(out_rois, rois, (size_t)rois_elems * sizeof(float),
                    cudaMemcpyDeviceToDevice, 0);
}

// round 8
// speedup vs baseline: 9.3019x; 1.1232x over previous
#include <cuda_runtime.h>
#include <cmath>

#define KMAX 100
#define NBKT 256
#define WPB  8      // warps per block, one (n,c) problem per warp (2 per SMSP)
#define TRN  128    // tranche size (candidates per NMS round)
#define SPT  4      // candidates per lane (TRN/32)

// Scratch (device globals — no allocation allowed).
__device__ float g_flat_scores[16 * 128 * KMAX];       // [N][C][K]
__device__ float g_flat_boxes [16 * 128 * KMAX * 4];   // [N][C][K][4]
__device__ float g_conf_t     [16 * 128 * 1024];       // [N][C][B] transposed

// ---------------------------------------------------------------------------
// Transpose conf [N][B][C+1] -> g_conf_t [N][C][B]  (drop background column)
// Also copies rois -> out_rois (folds away the graph memcpy node).
// ---------------------------------------------------------------------------
__global__ void transpose_conf_kernel(const float* __restrict__ conf,
                                      const float4* __restrict__ rois4,
                                      float4* __restrict__ out_rois4,
                                      int rois_vec4, int B, int C)
{
    __shared__ float tile[32][33];
    const int n  = blockIdx.z;
    const int b0 = blockIdx.x * 32;
    const int c0 = blockIdx.y * 32;
    const int tx = threadIdx.x, ty = threadIdx.y;   // (32, 8)
    const int tid = ty * 32 + tx;

    // rois passthrough, spread over the by==0 slice of the grid
    if (blockIdx.y == 0) {
        int flat = (blockIdx.z * gridDim.x + blockIdx.x) * 256 + tid;
        if (flat < rois_vec4) out_rois4[flat] = rois4[flat];
    }

    #pragma unroll
    for (int s = 0; s < 4; s++) {
        int b = b0 + ty + s * 8;
        int c = c0 + tx;
        if (b < B && c < C)
            tile[ty + s * 8][tx] = conf[((size_t)n * B + b) * (C + 1) + c];
    }
    __syncthreads();
    #pragma unroll
    for (int s = 0; s < 4; s++) {
        int c = c0 + ty + s * 8;
        int b = b0 + tx;
        if (b < B && c < C)
            g_conf_t[((size_t)n * C + c) * B + b] = tile[tx][ty + s * 8];
    }
}

// ---------------------------------------------------------------------------
// Warp-parallel threshold pickers over a 256-bucket histogram.
// ---------------------------------------------------------------------------
// Maximal window [t_lo, t_hi) with count <= limit (top-down contiguous).
__device__ __forceinline__ int pick_window_le(const unsigned* hist, int t_hi,
                                              int limit, int lane, int* cnt_out)
{
    const unsigned FULL = 0xffffffffu;
    unsigned s = 0;
    #pragma unroll
    for (int m = 0; m < 8; m++) {
        int k = 8 * lane + m;
        if (k < t_hi) s += hist[k];
    }
    unsigned cum = s;                                // suffix-inclusive scan
    #pragma unroll
    for (int off = 1; off < 32; off <<= 1) {
        unsigned o = __shfl_down_sync(FULL, cum, off);
        if (lane + off < 32) cum += o;
    }
    unsigned bal = __ballot_sync(FULL, cum <= (unsigned)limit);
    int t_lo, cnt;
    int l0 = (bal == 0) ? 32 : (__ffs(bal) - 1);
    if (l0 == 0) {
        t_lo = 0;
        cnt  = (int)__shfl_sync(FULL, cum, 0);
    } else {
        int rl = (l0 - 1 < 31) ? l0 - 1 : 31;
        unsigned below = (l0 <= 31) ? __shfl_sync(FULL, cum, l0) : 0u;
        if (l0 == 32) below = 0u;
        int tl = (8 * l0 < 256) ? 8 * l0 : 256;
        unsigned run = below;
        if (lane == rl) {
            #pragma unroll
            for (int m = 7; m >= 0; m--) {
                int k = 8 * rl + m;
                unsigned h = (k < t_hi) ? hist[k] : 0u;
                if (run + h <= (unsigned)limit) { run += h; tl = k; }
                else break;
            }
        }
        t_lo = __shfl_sync(FULL, tl, rl);
        cnt  = (int)__shfl_sync(FULL, run, rl);
    }
    if (t_lo >= t_hi) {          // even one bucket overflows: take it anyway
        t_lo = t_hi - 1;
        cnt  = (int)hist[t_lo];
    }
    *cnt_out = cnt;
    return t_lo;
}

// Minimal window [t_lo, 256) with count >= limit (include boundary-bucket ties).
__device__ __forceinline__ int pick_window_ge(const unsigned* hist, int limit,
                                              int lane, int* cnt_out)
{
    const unsigned FULL = 0xffffffffu;
    unsigned s = 0;
    #pragma unroll
    for (int m = 0; m < 8; m++) s += hist[8 * lane + m];
    unsigned cum = s;
    #pragma unroll
    for (int off = 1; off < 32; off <<= 1) {
        unsigned o = __shfl_down_sync(FULL, cum, off);
        if (lane + off < 32) cum += o;
    }
    unsigned bal = __ballot_sync(FULL, cum >= (unsigned)limit);
    int t_lo, cnt;
    if (bal == 0) {                       // fewer than limit valid total
        t_lo = 0;
        cnt  = (int)__shfl_sync(FULL, cum, 0);
    } else {
        int lp = 31 - __clz(bal);         // highest lane with suffix >= limit
        unsigned below = (lp < 31) ? __shfl_sync(FULL, cum, lp + 1) : 0u;
        int tl = 8 * (lp + 1);
        unsigned run = below;
        if (lane == lp) {
            #pragma unroll
            for (int m = 7; m >= 0; m--) {
                run += hist[8 * lp + m];
                tl = 8 * lp + m;
                if (run >= (unsigned)limit) break;
            }
        }
        t_lo = __shfl_sync(FULL, tl, lp);
        cnt  = (int)__shfl_sync(FULL, run, lp);
    }
    *cnt_out = cnt;
    return t_lo;
}

// ---------------------------------------------------------------------------
// Stage 1: one WARP per (n, c); 8 warps per 256-thread CTA.
// score load -> histogram -> threshold -> ballot compact (<=128) ->
// bitonic sort -> gather-decode (interleaved rank ownership r = lane+32q) ->
// UPPER-TRIANGLE suppression-mask matrix (lower triangle is don't-care since
// the scan consumes ranks in order) -> lane-0 bit-scan -> parallel epilogue.
// ---------------------------------------------------------------------------
__global__ __launch_bounds__(32 * WPB)
void decode_nms_kernel(const float* __restrict__ rois,
                       const float* __restrict__ deltas,
                       int B, int C, int NC, float hm1, float wm1)
{
    const int w    = threadIdx.x >> 5;
    const int lane = threadIdx.x & 31;
    const int pid  = blockIdx.x * WPB + w;
    if (pid >= NC) return;
    const int n = pid / C;
    const int c = pid % C;
    const unsigned FULL = 0xffffffffu;

    __shared__ unsigned           hist_s [WPB][NBKT];
    __shared__ unsigned long long ckey_s [WPB][TRN];
    __shared__ float4             rbox_s [WPB][TRN];
    __shared__ float              rarea_s[WPB][TRN];
    __shared__ uint4              mask_s [WPB][TRN];
    __shared__ float4             kbox_s [WPB][KMAX];
    __shared__ float              karea_s[WPB][KMAX];
    __shared__ int                sidx_s [WPB][KMAX];

    unsigned*           hist  = hist_s [w];
    unsigned long long* ckey  = ckey_s [w];
    float4*             rbox  = rbox_s [w];
    float*              rarea = rarea_s[w];
    uint4*              maskm = mask_s [w];
    float4*             kbox  = kbox_s [w];
    float*              karea = karea_s[w];
    int*                sidx  = sidx_s [w];

    for (int i = lane; i < NBKT; i += 32) hist[i] = 0u;
    __syncwarp();

    // ---- coalesced score load (transposed conf), MLP=8 ----
    const float* csrc = g_conf_t + ((size_t)n * C + c) * B;
    const int NV4 = B >> 2;          // B divisible by 4 (B=1000)
    float rs[32];
    #pragma unroll
    for (int u = 0; u < 8; u++) {
        int i4 = lane + 32 * u;
        float4 v = make_float4(0.f, 0.f, 0.f, 0.f);
        if (i4 < NV4) v = ((const float4*)csrc)[i4];
        rs[4*u+0] = (v.x > 0.05f) ? v.x : 0.f;
        rs[4*u+1] = (v.y > 0.05f) ? v.y : 0.f;
        rs[4*u+2] = (v.z > 0.05f) ? v.z : 0.f;
        rs[4*u+3] = (v.w > 0.05f) ? v.w : 0.f;
    }
    // b index of rs[e]: e = 4u + j  ->  b = 128*u + 4*lane + j

    #pragma unroll
    for (int e = 0; e < 32; e++) {
        float v = rs[e];
        if (v > 0.f) atomicAdd(&hist[min((int)(v * 256.f), 255)], 1u);
    }
    __syncwarp();

    float* fs = g_flat_scores + ((size_t)n * C + c) * KMAX;
    float* fb = g_flat_boxes  + ((size_t)n * C + c) * KMAX * 4;

    int kept = 0;
    int t_hi = NBKT;

    while (kept < KMAX && t_hi > 0) {
        int cnt;
        const int t_lo = pick_window_le(hist, t_hi, TRN, lane, &cnt);
        const int w_hi = t_hi;          // window = [t_lo, w_hi)
        t_hi = t_lo;
        if (cnt > TRN) cnt = TRN;
        if (cnt == 0) continue;

        // ---- ballot compaction ----
        unsigned base = 0;
        #pragma unroll
        for (int e = 0; e < 32; e++) {
            float v = rs[e];
            int bk = (v > 0.f) ? min((int)(v * 256.f), 255) : -1;
            bool take = (bk >= t_lo) && (bk < w_hi);
            unsigned m = __ballot_sync(FULL, take);
            if (take) {
                unsigned pos = base + __popc(m & ((1u << lane) - 1u));
                if (pos < (unsigned)TRN) {
                    int b = 128 * (e >> 2) + 4 * lane + (e & 3);
                    ckey[pos] = ((unsigned long long)__float_as_uint(v) << 10)
                              | (unsigned long long)(1023 - b);
                }
            }
            base += __popc(m);
        }
        __syncwarp();

        int P = 1; while (P < cnt) P <<= 1;
        for (int i = cnt + lane; i < P; i += 32) ckey[i] = 0ull;
        __syncwarp();

        // ---- bitonic sort desc by (score, ~b) ----
        for (int k = 2; k <= P; k <<= 1) {
            for (int j = k >> 1; j > 0; j >>= 1) {
                for (int p = lane; p < (P >> 1); p += 32) {
                    int i = ((p & ~(j - 1)) << 1) | (p & (j - 1));
                    int l = i | j;
                    unsigned long long a = ckey[i], bb = ckey[l];
                    bool desc = ((i & k) == 0);
                    if (desc ? (a < bb) : (a > bb)) { ckey[i] = bb; ckey[l] = a; }
                }
                __syncwarp();
            }
        }

        // ---- gather-decode: INTERLEAVED ranks, lane owns r = lane + 32q ----
        float by1[SPT], bx1[SPT], by2[SPT], bx2[SPT], bar_[SPT];
        unsigned alive = 0;
        #pragma unroll
        for (int q = 0; q < SPT; q++) {
            int r = lane + 32 * q;
            float yy1 = 0.f, xx1 = 0.f, yy2 = 0.f, xx2 = 0.f, ar = 0.f;
            if (r < cnt) {
                unsigned long long key = ckey[r];
                int b = 1023 - (int)(key & 1023ull);
                float4 rr = ((const float4*)rois)[(size_t)n * B + b];
                float w0 = rr.w - rr.y + 1.0f;
                float h0 = rr.z - rr.x + 1.0f;
                float x0 = rr.y + 0.5f * w0;
                float y0 = rr.x + 0.5f * h0;
                float4 d = ((const float4*)deltas)[((size_t)n * B + b) * C + c];
                float cx = (d.x * 0.1f) * w0 + x0;
                float cy = (d.y * 0.1f) * h0 + y0;
                float ww = __expf(d.z * 0.2f) * w0;
                float hh = __expf(d.w * 0.2f) * h0;
                xx1 = fminf(fmaxf(cx - 0.5f * ww, 0.0f), wm1);
                yy1 = fminf(fmaxf(cy - 0.5f * hh, 0.0f), hm1);
                xx2 = fminf(fmaxf(cx + 0.5f * ww, 0.0f), wm1);
                yy2 = fminf(fmaxf(cy + 0.5f * hh, 0.0f), hm1);
                ar  = (yy2 - yy1) * (xx2 - xx1);
                rbox[r]  = make_float4(yy1, xx1, yy2, xx2);
                rarea[r] = ar;
                alive |= (1u << q);
            }
            by1[q] = yy1; bx1[q] = xx1; by2[q] = yy2; bx2[q] = xx2; bar_[q] = ar;
        }
        __syncwarp();

        // ---- later tranches: pre-suppress vs already-kept boxes ----
        for (int kk = 0; kk < kept; kk++) {
            float4 kb = kbox[kk];
            float  ka = karea[kk];
            #pragma unroll
            for (int q = 0; q < SPT; q++) {
                if (alive & (1u << q)) {
                    float iy1 = fmaxf(kb.x, by1[q]);
                    float ix1 = fmaxf(kb.y, bx1[q]);
                    float iy2 = fminf(kb.z, by2[q]);
                    float ix2 = fminf(kb.w, bx2[q]);
                    float it  = fmaxf(iy2 - iy1, 0.f) * fmaxf(ix2 - ix1, 0.f);
                    float un  = fmaxf(ka + bar_[q] - it, 1e-8f);
                    if (it > 0.5f * un) alive &= ~(1u << q);
                }
            }
        }

        // ---- upper-triangle suppression-mask matrix ----
        // Row r = lane + 32q. Block wb covers s in [32wb, 32wb+32). For q > wb
        // every s in the block is < r (below diagonal = don't-care) -> skip at
        // compile time: only q <= wb computed (10 of 16 blocks). Self-bit set
        // via s == r so the scan self-clears the picked rank.
        unsigned acc[SPT][4];
        #pragma unroll
        for (int q = 0; q < SPT; q++) {
            acc[q][0] = 0u; acc[q][1] = 0u; acc[q][2] = 0u; acc[q][3] = 0u;
        }
        #pragma unroll
        for (int wb = 0; wb < 4; wb++) {
            if (32 * wb >= cnt) break;
            #pragma unroll 4
            for (int sb = 0; sb < 32; sb++) {
                int s = 32 * wb + sb;
                float4 bs = rbox[s];          // broadcast LDS
                float  as_ = rarea[s];
                #pragma unroll
                for (int q = 0; q <= wb && q < SPT; q++) {
                    float iy1 = fmaxf(bs.x, by1[q]);
                    float ix1 = fmaxf(bs.y, bx1[q]);
                    float iy2 = fminf(bs.z, by2[q]);
                    float ix2 = fminf(bs.w, bx2[q]);
                    float it  = fmaxf(iy2 - iy1, 0.f) * fmaxf(ix2 - ix1, 0.f);
                    float un  = fmaxf(as_ + bar_[q] - it, 1e-8f);
                    bool sup  = (it > 0.5f * un);
                    if (q == wb) sup = sup || (sb == lane);   // self-bit
                    if (sup) acc[q][wb] |= (1u << sb);
                }
            }
        }
        #pragma unroll
        for (int q = 0; q < SPT; q++)
            maskm[lane + 32 * q] =
                make_uint4(acc[q][0], acc[q][1], acc[q][2], acc[q][3]);
        __syncwarp();

        // ---- alive words via ballot (word q = ranks [32q, 32q+32)) ----
        unsigned a0 = __ballot_sync(FULL, (alive >> 0) & 1u);
        unsigned a1 = __ballot_sync(FULL, (alive >> 1) & 1u);
        unsigned a2 = __ballot_sync(FULL, (alive >> 2) & 1u);
        unsigned a3 = __ballot_sync(FULL, (alive >> 3) & 1u);

        // ---- serial bit-scan on lane 0 (short chain: ffs -> LDS -> AND) ----
        int kn = 0;
        if (lane == 0) {
            const int room = KMAX - kept;
            while (kn < room) {
                int r;
                if (a0)      r = __ffs(a0) - 1;
                else if (a1) r = 31 + __ffs(a1);
                else if (a2) r = 63 + __ffs(a2);
                else if (a3) r = 95 + __ffs(a3);
                else break;
                sidx[kn++] = r;
                uint4 m = maskm[r];        // LDS.128 (has self-bit)
                a0 &= ~m.x; a1 &= ~m.y; a2 &= ~m.z; a3 &= ~m.w;
            }
        }
        kn = __shfl_sync(FULL, kn, 0);

        // ---- parallel output epilogue ----
        for (int i = lane; i < kn; i += 32) {
            int r = sidx[i];
            float4 bb = rbox[r];
            fs[kept + i] = __uint_as_float((unsigned)(ckey[r] >> 10));
            ((float4*)fb)[kept + i] = bb;
            kbox[kept + i]  = bb;
            karea[kept + i] = rarea[r];
        }
        kept += kn;
        __syncwarp();
    }

    for (int kk = kept + lane; kk < KMAX; kk += 32) fs[kk] = 0.0f;
}

// ---------------------------------------------------------------------------
// Stage 2: per image, exact rank-100 via batched loads + histogram + sort.
// ---------------------------------------------------------------------------
__global__ __launch_bounds__(256)
void topk_kernel(float* __restrict__ out_boxes,
                 float* __restrict__ out_scores,
                 float* __restrict__ out_classes,
                 float* __restrict__ out_numdets,
                 int C)
{
    const int n    = blockIdx.x;
    const int tid  = threadIdx.x;
    const int lane = tid & 31;
    const int CK   = C * KMAX;                 // 8000

    __shared__ unsigned           hist[NBKT];
    __shared__ unsigned long long key[1024];
    __shared__ unsigned           scnt;

    for (int i = tid; i < NBKT; i += 256) hist[i] = 0u;
    if (tid == 0) scnt = 0u;
    __syncthreads();

    // batched register loads, MLP=8
    const float* src = g_flat_scores + (size_t)n * CK;
    const int NV4 = CK >> 2;
    float4 v4[8];
    #pragma unroll
    for (int u = 0; u < 8; u++) {
        int i4 = tid + 256 * u;
        v4[u] = (i4 < NV4) ? ((const float4*)src)[i4]
                           : make_float4(0.f, 0.f, 0.f, 0.f);
    }
    #pragma unroll
    for (int u = 0; u < 8; u++) {
        float vv[4] = {v4[u].x, v4[u].y, v4[u].z, v4[u].w};
        #pragma unroll
        for (int j = 0; j < 4; j++)
            if (vv[j] > 0.f)
                atomicAdd(&hist[min((int)(vv[j] * 256.f), 255)], 1u);
    }
    __syncthreads();

    int cnt_est;
    const int t_lo = pick_window_ge(hist, KMAX, lane, &cnt_est);  // all warps same

    #pragma unroll
    for (int u = 0; u < 8; u++) {
        float vv[4] = {v4[u].x, v4[u].y, v4[u].z, v4[u].w};
        #pragma unroll
        for (int j = 0; j < 4; j++) {
            float v = vv[j];
            if (v > 0.f && min((int)(v * 256.f), 255) >= t_lo) {
                unsigned p = atomicAdd(&scnt, 1u);
                if (p < 1024u) {
                    int i = 4 * (tid + 256 * u) + j;
                    key[p] = ((unsigned long long)__float_as_uint(v) << 13)
                           | (unsigned long long)(8191 - i);
                }
            }
        }
    }
    __syncthreads();
    const int cnt = min((int)scnt, 1024);

    int P = 2; while (P < cnt) P <<= 1;
    for (int i = cnt + tid; i < P; i += 256) key[i] = 0ull;
    __syncthreads();

    for (int k = 2; k <= P; k <<= 1) {
        for (int j = k >> 1; j > 0; j >>= 1) {
            for (int p = tid; p < (P >> 1); p += 256) {
                int i = ((p & ~(j - 1)) << 1) | (p & (j - 1));
                int l = i | j;
                unsigned long long a = key[i], b = key[l];
                bool desc = ((i & k) == 0);
                if (desc ? (a < b) : (a > b)) { key[i] = b; key[l] = a; }
            }
            __syncthreads();
        }
    }

    if (tid < KMAX) {
        unsigned long long kk = (tid < cnt) ? key[tid] : 0ull;
        bool valid = (tid < cnt) && (kk != 0ull);
        float s = __uint_as_float((unsigned)(kk >> 13));
        int  fi = 8191 - (int)(kk & 8191ull);
        out_scores [n * KMAX + tid] = valid ? s : 0.f;
        out_classes[n * KMAX + tid] = valid ? (float)(fi / KMAX) : 0.f;
        float4 bb = make_float4(0.f, 0.f, 0.f, 0.f);
        if (valid) bb = ((const float4*)g_flat_boxes)[(size_t)n * CK + fi];
        ((float4*)out_boxes)[n * KMAX + tid] = bb;
    }
    if (tid == 0) out_numdets[n] = (float)min(cnt, KMAX);
}

// ---------------------------------------------------------------------------
extern "C" void kernel_launch(void* const* d_in, const int* in_sizes, int n_in,
                              void* d_out, int out_size)
{
    const float* rois   = (const float*)d_in[0];
    const float* conf   = (const float*)d_in[1];
    const float* deltas = (const float*)d_in[2];

    const int rois_elems = in_sizes[0];
    const int N = (out_size - rois_elems) / (6 * KMAX + 1);
    const int B = rois_elems / (4 * N);
    const int C = in_sizes[2] / ((size_t)N * B * 4);
    const int HW = in_sizes[3] / (3 * N);
    const int H = (int)(sqrt((double)HW) + 0.5);   // square image
    const float hm1 = (float)(H - 1);
    const float wm1 = (float)(H - 1);

    float* out         = (float*)d_out;
    float* out_boxes   = out;
    float* out_scores  = out + (size_t)N * KMAX * 4;
    float* out_classes = out + (size_t)N * KMAX * 5;
    float* out_numdets = out + (size_t)N * KMAX * 6;
    float* out_rois    = out + (size_t)N * KMAX * 6 + N;

    {
        dim3 grid((B + 31) / 32, (C + 31) / 32, N);
        dim3 block(32, 8);
        transpose_conf_kernel<<<grid, block>>>(conf, (const float4*)rois,
                                               (float4*)out_rois,
                                               rois_elems / 4, B, C);
    }
    {
        const int NC = N * C;
        decode_nms_kernel<<<(NC + WPB - 1) / WPB, 32 * WPB>>>(
            rois, deltas, B, C, NC, hm1, wm1);
    }
    topk_kernel<<<N, 256>>>(out_boxes, out_scores, out_classes, out_numdets, C);
}